// round 1
// baseline (speedup 1.0000x reference)
#include <cuda_runtime.h>
#include <math.h>

#define BB 32
#define SS 4096
#define HID 512
#define MEMD 512
#define ATT 512

// Scratch (no allocs allowed in kernel_launch)
__device__ float g_scores[BB * SS];
__device__ float g_h[BB * ATT];

// ---------------------------------------------------------------------------
// Kernel 0: zero score scratch + context region of output
// ---------------------------------------------------------------------------
__global__ void zero_kernel(float* __restrict__ out_ctx) {
    int i = blockIdx.x * blockDim.x + threadIdx.x;
    if (i < BB * SS) g_scores[i] = 0.0f;
    if (i < BB * MEMD) out_ctx[i] = 0.0f;
}

// ---------------------------------------------------------------------------
// Kernel 1: h[b][a] = sum_d hidden[b][d] * W_h[d][a]
// grid = B, block = 512
// ---------------------------------------------------------------------------
__global__ void h_kernel(const float* __restrict__ hidden,
                         const float* __restrict__ W_h) {
    __shared__ float sh[HID];
    int b = blockIdx.x;
    int a = threadIdx.x;
    sh[a] = hidden[b * HID + a];
    __syncthreads();
    float acc = 0.0f;
#pragma unroll 8
    for (int d = 0; d < HID; d++) {
        acc += sh[d] * W_h[d * ATT + a];
    }
    g_h[b * ATT + a] = acc;
}

// ---------------------------------------------------------------------------
// Kernel 2: fused GEMM + tanh + v-dot reduction into scores
//   C[row][n] = sum_k memory[row][k] * W_m[k][n]        (row = b*S + s)
//   score[row] += sum_n tanh(C + h[b][n] + cov[row]*W_c[n]) * v[n]
// Tile: 128 rows x 128 cols, K-step 8, 256 threads, 8x8 per-thread microtile.
// grid = (1024, 4), block = 256
// ---------------------------------------------------------------------------
#define Bb_M 128
#define Bb_N 128
#define Bb_K 8
#define T_M 8
#define T_N 8

__global__ __launch_bounds__(256) void score_kernel(
    const float* __restrict__ memory,
    const float* __restrict__ W_m,
    const float* __restrict__ coverage,
    const float* __restrict__ W_c,
    const float* __restrict__ v) {

    __shared__ float As[Bb_K][Bb_M + 4];   // A transposed: As[k][m]
    __shared__ float Bs[Bb_K][Bb_N];       // Bs[k][n]
    __shared__ float sred[Bb_M][16];       // per-row partial reduction

    const int tid = threadIdx.x;
    const long row0 = (long)blockIdx.x * Bb_M;
    const int n0 = blockIdx.y * Bb_N;

    // A-load mapping: 2 float4 per row-slab of 8 k's
    const int lm = tid >> 1;           // 0..127
    const int lk4 = (tid & 1) * 4;     // 0 or 4
    // B-load mapping: one k-row of 128 floats per warp
    const int bk = tid >> 5;           // 0..7
    const int bn4 = (tid & 31) * 4;    // 0..124

    // compute mapping
    const int trow = tid >> 4;         // 0..15
    const int tcol = tid & 15;         // 0..15
    const int m0 = trow * T_M;
    const int nn0 = tcol * T_N;

    float acc[T_M][T_N];
#pragma unroll
    for (int i = 0; i < T_M; i++)
#pragma unroll
        for (int j = 0; j < T_N; j++) acc[i][j] = 0.0f;

    for (int k0 = 0; k0 < MEMD; k0 += Bb_K) {
        float4 av = *reinterpret_cast<const float4*>(
            &memory[(row0 + lm) * (long)MEMD + k0 + lk4]);
        As[lk4 + 0][lm] = av.x;
        As[lk4 + 1][lm] = av.y;
        As[lk4 + 2][lm] = av.z;
        As[lk4 + 3][lm] = av.w;
        *reinterpret_cast<float4*>(&Bs[bk][bn4]) =
            *reinterpret_cast<const float4*>(&W_m[(k0 + bk) * ATT + n0 + bn4]);
        __syncthreads();

#pragma unroll
        for (int k = 0; k < Bb_K; k++) {
            float a[T_M], bb[T_N];
            *reinterpret_cast<float4*>(&a[0]) =
                *reinterpret_cast<const float4*>(&As[k][m0]);
            *reinterpret_cast<float4*>(&a[4]) =
                *reinterpret_cast<const float4*>(&As[k][m0 + 4]);
            *reinterpret_cast<float4*>(&bb[0]) =
                *reinterpret_cast<const float4*>(&Bs[k][nn0]);
            *reinterpret_cast<float4*>(&bb[4]) =
                *reinterpret_cast<const float4*>(&Bs[k][nn0 + 4]);
#pragma unroll
            for (int i = 0; i < T_M; i++)
#pragma unroll
                for (int j = 0; j < T_N; j++)
                    acc[i][j] += a[i] * bb[j];
        }
        __syncthreads();
    }

    // Epilogue: add h + coverage*W_c, tanh, dot with v (partial over 128 cols)
    const int b = (int)(row0 / SS);

    float wc[T_N], vv[T_N], hh[T_N];
#pragma unroll
    for (int j = 0; j < T_N; j++) {
        int a_idx = n0 + nn0 + j;
        wc[j] = W_c[a_idx];
        vv[j] = v[a_idx];
        hh[j] = g_h[b * ATT + a_idx];
    }

#pragma unroll
    for (int i = 0; i < T_M; i++) {
        long grow = row0 + m0 + i;
        float cov = coverage[grow];
        float p = 0.0f;
#pragma unroll
        for (int j = 0; j < T_N; j++) {
            float val = acc[i][j] + hh[j] + cov * wc[j];
            p += tanhf(val) * vv[j];
        }
        sred[m0 + i][tcol] = p;
    }
    __syncthreads();

    if (tid < Bb_M) {
        float s = 0.0f;
#pragma unroll
        for (int c = 0; c < 16; c++) s += sred[tid][c];
        atomicAdd(&g_scores[row0 + tid], s);
    }
}

// ---------------------------------------------------------------------------
// Kernel 3: softmax over S per batch (with pad mask)
// grid = B, block = 1024. attn written to d_out + B*MEM.
// ---------------------------------------------------------------------------
__global__ void softmax_kernel(const unsigned char* __restrict__ pad,
                               float* __restrict__ attn) {
    __shared__ float red[1024];
    const int b = blockIdx.x;
    const int tid = threadIdx.x;

    float mx = -INFINITY;
    for (int s = tid; s < SS; s += 1024) {
        float sc = pad[b * SS + s] ? -INFINITY : g_scores[b * SS + s];
        mx = fmaxf(mx, sc);
    }
    red[tid] = mx;
    __syncthreads();
    for (int off = 512; off > 0; off >>= 1) {
        if (tid < off) red[tid] = fmaxf(red[tid], red[tid + off]);
        __syncthreads();
    }
    mx = red[0];
    __syncthreads();

    float sum = 0.0f;
    for (int s = tid; s < SS; s += 1024) {
        float sc = pad[b * SS + s] ? -INFINITY : g_scores[b * SS + s];
        float e = expf(sc - mx);
        attn[b * SS + s] = e;
        sum += e;
    }
    red[tid] = sum;
    __syncthreads();
    for (int off = 512; off > 0; off >>= 1) {
        if (tid < off) red[tid] += red[tid + off];
        __syncthreads();
    }
    float inv = 1.0f / red[0];
    for (int s = tid; s < SS; s += 1024) {
        attn[b * SS + s] *= inv;
    }
}

// ---------------------------------------------------------------------------
// Kernel 4: context[b][d] = sum_s attn[b][s] * memory[b][s][d]
// grid = (B, 8 s-chunks of 512), block = 512 (one thread per d)
// ---------------------------------------------------------------------------
__global__ void context_kernel(const float* __restrict__ memory,
                               const float* __restrict__ attn,
                               float* __restrict__ ctx) {
    __shared__ float w[512];
    const int b = blockIdx.x;
    const int s0 = blockIdx.y * 512;
    const int d = threadIdx.x;

    w[d] = attn[b * SS + s0 + d];
    __syncthreads();

    float acc = 0.0f;
    const float* mbase = memory + ((long)b * SS + s0) * MEMD + d;
#pragma unroll 4
    for (int s = 0; s < 512; s++) {
        acc += w[s] * mbase[(long)s * MEMD];
    }
    atomicAdd(&ctx[b * MEMD + d], acc);
}

// ---------------------------------------------------------------------------
// Launch
// Inputs (metadata order):
//   0 hidden (B,HID) f32       1 memory (B,S,MEM) f32
//   2 mem_pad (B,S) bool       3 coverage (B,S) f32
//   4 W_h (HID,ATT) f32        5 W_m (MEM,ATT) f32
//   6 W_c (ATT,) f32           7 v (ATT,) f32
// Output: [context (B*MEM) | attn (B*S)] f32
// ---------------------------------------------------------------------------
extern "C" void kernel_launch(void* const* d_in, const int* in_sizes, int n_in,
                              void* d_out, int out_size) {
    const float* hidden   = (const float*)d_in[0];
    const float* memory   = (const float*)d_in[1];
    const unsigned char* mem_pad = (const unsigned char*)d_in[2];
    const float* coverage = (const float*)d_in[3];
    const float* W_h      = (const float*)d_in[4];
    const float* W_m      = (const float*)d_in[5];
    const float* W_c      = (const float*)d_in[6];
    const float* v        = (const float*)d_in[7];

    float* out = (float*)d_out;
    float* out_ctx = out;                 // B*MEM floats
    float* out_attn = out + BB * MEMD;    // B*S floats

    zero_kernel<<<(BB * SS + 255) / 256, 256>>>(out_ctx);
    h_kernel<<<BB, 512>>>(hidden, W_h);
    {
        dim3 grid(BB * SS / Bb_M, ATT / Bb_N);
        score_kernel<<<grid, 256>>>(memory, W_m, coverage, W_c, v);
    }
    softmax_kernel<<<BB, 1024>>>(mem_pad, out_attn);
    {
        dim3 grid(BB, SS / 512);
        context_kernel<<<grid, 512>>>(memory, out_attn, out_ctx);
    }
}

// round 4
// speedup vs baseline: 3.1063x; 3.1063x over previous
#include <cuda_runtime.h>
#include <math.h>
#include <stdint.h>

#define BB   32
#define SS   4096
#define HID  512
#define MEMD 512
#define ATT  512

// ------------------------------- scratch -----------------------------------
__device__ float g_scores[BB * SS];
__device__ float g_h[BB * ATT];
__device__ float g_Wr[MEMD * ATT];   // W_m tf32-rounded, same [k][n] layout

// ------------------------------- helpers -----------------------------------
__device__ __forceinline__ uint32_t smem_u32(const void* p) {
    return (uint32_t)__cvta_generic_to_shared(p);
}
__device__ __forceinline__ void cp16(uint32_t dst, const float* src) {
    asm volatile("cp.async.cg.shared.global [%0], [%1], 16;\n" :: "r"(dst), "l"(src));
}
__device__ __forceinline__ void cp_commit() { asm volatile("cp.async.commit_group;\n" ::: "memory"); }
template <int N>
__device__ __forceinline__ void cp_wait() {
    asm volatile("cp.async.wait_group %0;\n" :: "n"(N) : "memory");
}
__device__ __forceinline__ uint32_t f2tf32(float x) {
    uint32_t r;
    asm("cvt.rna.tf32.f32 %0, %1;" : "=r"(r) : "f"(x));
    return r;
}
__device__ __forceinline__ void mma_tf32(float* d, const uint32_t* a, const uint32_t* b) {
    asm volatile(
        "mma.sync.aligned.m16n8k8.row.col.f32.tf32.tf32.f32 "
        "{%0,%1,%2,%3}, {%4,%5,%6,%7}, {%8,%9}, {%0,%1,%2,%3};"
        : "+f"(d[0]), "+f"(d[1]), "+f"(d[2]), "+f"(d[3])
        : "r"(a[0]), "r"(a[1]), "r"(a[2]), "r"(a[3]), "r"(b[0]), "r"(b[1]));
}

// ---------------------------------------------------------------------------
// zero: scores scratch + context output region
// ---------------------------------------------------------------------------
__global__ void zero_kernel(float* __restrict__ out_ctx) {
    int i = blockIdx.x * blockDim.x + threadIdx.x;
    if (i < BB * SS) g_scores[i] = 0.0f;
    if (i < BB * MEMD) out_ctx[i] = 0.0f;
}

// ---------------------------------------------------------------------------
// pre-round W_m to tf32 (rna), same layout
// ---------------------------------------------------------------------------
__global__ void round_wm(const float* __restrict__ Wm) {
    int i = blockIdx.x * blockDim.x + threadIdx.x;
    if (i < MEMD * ATT) {
        uint32_t r = f2tf32(Wm[i]);
        g_Wr[i] = __uint_as_float(r);
    }
}

// ---------------------------------------------------------------------------
// h[b][a] = hidden[b] . W_h[:,a]   grid=B, block=512
// ---------------------------------------------------------------------------
__global__ void h_kernel(const float* __restrict__ hidden,
                         const float* __restrict__ W_h) {
    __shared__ float sh[HID];
    int b = blockIdx.x;
    int a = threadIdx.x;
    sh[a] = hidden[b * HID + a];
    __syncthreads();
    float acc = 0.0f;
#pragma unroll 8
    for (int d = 0; d < HID; d++) acc += sh[d] * W_h[d * ATT + a];
    g_h[b * ATT + a] = acc;
}

// ---------------------------------------------------------------------------
// Score GEMM (tf32 mma.sync) fused with tanh/v epilogue.
//   C[row, n] = memory[row, :] @ W_m[:, n]  (row = b*S+s, 131072 x 512 x 512)
//   score[row] += sum_n tanh(C + h[b,n] + cov[row]*W_c[n]) * v[n]
// CTA tile 128x128x32, 256 threads (8 warps: 4M x 2N), warp tile 32x64.
// grid = (4 n-tiles, 1024 m-tiles), dyn smem ~76KB, 2 CTAs/SM.
// ---------------------------------------------------------------------------
#define BM 128
#define BN 128
#define BK 32
#define AST 36     // A smem row stride (floats): conflict-free fragment LDS
#define BST 136    // B smem row stride (floats)
#define A_TILE (BM * AST)   // 4608 floats
#define B_TILE (BK * BST)   // 4352 floats
#define NSTAGE (MEMD / BK)  // 16

__global__ void __launch_bounds__(256, 2) score_mma(
    const float* __restrict__ Amem,
    const float* __restrict__ coverage,
    const float* __restrict__ Wc,
    const float* __restrict__ vvec) {

    extern __shared__ float dsm[];
    float* As   = dsm;                       // 2 * A_TILE
    float* Bs   = As + 2 * A_TILE;           // 2 * B_TILE
    float* sh_h = Bs + 2 * B_TILE;           // 512 (absolute a index)
    float* sh_wc = sh_h + 512;               // 512
    float* sh_v  = sh_wc + 512;              // 512

    const int tid   = threadIdx.x;
    const int lane  = tid & 31;
    const int wid   = tid >> 5;
    const int warpM = wid & 3;     // 0..3
    const int warpN = wid >> 2;    // 0..1
    const int g     = lane >> 2;   // groupID 0..7
    const int tg    = lane & 3;    // thread-in-group 0..3

    const int  n0   = blockIdx.x * BN;
    const long row0 = (long)blockIdx.y * BM;
    const int  b    = (int)(row0 >> 12);

    for (int i = tid; i < 512; i += 256) {
        sh_h[i]  = g_h[b * 512 + i];
        sh_wc[i] = Wc[i];
        sh_v[i]  = vvec[i];
    }

    float acc[2][8][4];
#pragma unroll
    for (int i = 0; i < 2; i++)
#pragma unroll
        for (int j = 0; j < 8; j++)
#pragma unroll
            for (int c = 0; c < 4; c++) acc[i][j][c] = 0.0f;

    auto load_stage = [&](int s) {
        const int buf = s & 1;
        const int k0 = s * BK;
        uint32_t Abu = smem_u32(As + buf * A_TILE);
        uint32_t Bbu = smem_u32(Bs + buf * B_TILE);
#pragma unroll
        for (int j = 0; j < 4; j++) {
            int chunk = tid + 256 * j;          // 0..1023
            int r = chunk >> 3, c4 = chunk & 7; // 128 rows x 8 float4
            cp16(Abu + (r * AST + c4 * 4) * 4, Amem + (row0 + r) * 512 + k0 + c4 * 4);
        }
#pragma unroll
        for (int j = 0; j < 4; j++) {
            int chunk = tid + 256 * j;
            int r = chunk >> 5, c4 = chunk & 31; // 32 rows x 32 float4
            cp16(Bbu + (r * BST + c4 * 4) * 4, g_Wr + (k0 + r) * 512 + n0 + c4 * 4);
        }
        cp_commit();
    };

    load_stage(0);

    for (int s = 0; s < NSTAGE; s++) {
        if (s + 1 < NSTAGE) {
            load_stage(s + 1);
            cp_wait<1>();
        } else {
            cp_wait<0>();
        }
        __syncthreads();

        const int buf = s & 1;
        const float* Ab = As + buf * A_TILE;
        const float* Bb = Bs + buf * B_TILE;

#pragma unroll
        for (int ks = 0; ks < 4; ks++) {
            uint32_t af[2][4];
#pragma unroll
            for (int i = 0; i < 2; i++) {
                int r = warpM * 32 + i * 16 + g;
                int c = ks * 8 + tg;
                af[i][0] = f2tf32(Ab[r * AST + c]);
                af[i][1] = f2tf32(Ab[(r + 8) * AST + c]);
                af[i][2] = f2tf32(Ab[r * AST + c + 4]);
                af[i][3] = f2tf32(Ab[(r + 8) * AST + c + 4]);
            }
            uint32_t bf[8][2];
#pragma unroll
            for (int j = 0; j < 8; j++) {
                int n = warpN * 64 + j * 8 + g;
                int k = ks * 8 + tg;
                bf[j][0] = __float_as_uint(Bb[k * BST + n]);
                bf[j][1] = __float_as_uint(Bb[(k + 4) * BST + n]);
            }
#pragma unroll
            for (int i = 0; i < 2; i++)
#pragma unroll
                for (int j = 0; j < 8; j++)
                    mma_tf32(acc[i][j], af[i], bf[j]);
        }
        __syncthreads();
    }

    // ---- epilogue: tanh + v-dot partial over this CTA's 128 n-cols ----
    // NOTE: sh_h/sh_wc/sh_v are indexed by ABSOLUTE attention index.
#pragma unroll
    for (int i = 0; i < 2; i++) {
        const int r_lo = warpM * 32 + i * 16 + g;
        const int r_hi = r_lo + 8;
        const float cov_lo = coverage[row0 + r_lo];
        const float cov_hi = coverage[row0 + r_hi];
        float p_lo = 0.0f, p_hi = 0.0f;
#pragma unroll
        for (int j = 0; j < 8; j++) {
            const int nb = n0 + warpN * 64 + j * 8 + tg * 2;   // absolute col
            const float h0 = sh_h[nb + 0], h1 = sh_h[nb + 1];
            const float w0 = sh_wc[nb + 0], w1 = sh_wc[nb + 1];
            const float v0 = sh_v[nb + 0], v1 = sh_v[nb + 1];
            p_lo += tanhf(acc[i][j][0] + h0 + cov_lo * w0) * v0;
            p_lo += tanhf(acc[i][j][1] + h1 + cov_lo * w1) * v1;
            p_hi += tanhf(acc[i][j][2] + h0 + cov_hi * w0) * v0;
            p_hi += tanhf(acc[i][j][3] + h1 + cov_hi * w1) * v1;
        }
        p_lo += __shfl_xor_sync(0xffffffffu, p_lo, 1);
        p_lo += __shfl_xor_sync(0xffffffffu, p_lo, 2);
        p_hi += __shfl_xor_sync(0xffffffffu, p_hi, 1);
        p_hi += __shfl_xor_sync(0xffffffffu, p_hi, 2);
        if (tg == 0) {
            atomicAdd(&g_scores[row0 + r_lo], p_lo);
            atomicAdd(&g_scores[row0 + r_hi], p_hi);
        }
    }
}

// ---------------------------------------------------------------------------
// Softmax over S per batch (with pad mask). grid=B, block=1024.
// ---------------------------------------------------------------------------
__global__ void softmax_kernel(const unsigned char* __restrict__ pad,
                               float* __restrict__ attn) {
    __shared__ float red[1024];
    const int b = blockIdx.x;
    const int tid = threadIdx.x;

    float mx = -INFINITY;
    for (int s = tid; s < SS; s += 1024) {
        float sc = pad[b * SS + s] ? -INFINITY : g_scores[b * SS + s];
        mx = fmaxf(mx, sc);
    }
    red[tid] = mx;
    __syncthreads();
    for (int off = 512; off > 0; off >>= 1) {
        if (tid < off) red[tid] = fmaxf(red[tid], red[tid + off]);
        __syncthreads();
    }
    mx = red[0];
    __syncthreads();

    float sum = 0.0f;
    for (int s = tid; s < SS; s += 1024) {
        float sc = pad[b * SS + s] ? -INFINITY : g_scores[b * SS + s];
        float e = expf(sc - mx);
        attn[b * SS + s] = e;
        sum += e;
    }
    red[tid] = sum;
    __syncthreads();
    for (int off = 512; off > 0; off >>= 1) {
        if (tid < off) red[tid] += red[tid + off];
        __syncthreads();
    }
    float inv = 1.0f / red[0];
    for (int s = tid; s < SS; s += 1024) attn[b * SS + s] *= inv;
}

// ---------------------------------------------------------------------------
// context[b][d] = sum_s attn[b][s] * memory[b][s][d]. grid=(B,8), block=512.
// ---------------------------------------------------------------------------
__global__ void context_kernel(const float* __restrict__ memory,
                               const float* __restrict__ attn,
                               float* __restrict__ ctx) {
    __shared__ float w[512];
    const int b = blockIdx.x;
    const int s0 = blockIdx.y * 512;
    const int d = threadIdx.x;

    w[d] = attn[b * SS + s0 + d];
    __syncthreads();

    float acc = 0.0f;
    const float* mbase = memory + ((long)b * SS + s0) * MEMD + d;
#pragma unroll 4
    for (int s = 0; s < 512; s++) acc += w[s] * mbase[(long)s * MEMD];
    atomicAdd(&ctx[b * MEMD + d], acc);
}

// ---------------------------------------------------------------------------
// Launch.  Inputs (metadata order):
//   0 hidden | 1 memory | 2 mem_pad | 3 coverage | 4 W_h | 5 W_m | 6 W_c | 7 v
// Output: [context (B*MEM) | attn (B*S)] f32
// ---------------------------------------------------------------------------
#define SMEM_DYN ((2 * A_TILE + 2 * B_TILE + 3 * 512) * 4)

extern "C" void kernel_launch(void* const* d_in, const int* in_sizes, int n_in,
                              void* d_out, int out_size) {
    const float* hidden   = (const float*)d_in[0];
    const float* memory   = (const float*)d_in[1];
    const unsigned char* mem_pad = (const unsigned char*)d_in[2];
    const float* coverage = (const float*)d_in[3];
    const float* W_h      = (const float*)d_in[4];
    const float* W_m      = (const float*)d_in[5];
    const float* W_c      = (const float*)d_in[6];
    const float* v        = (const float*)d_in[7];

    float* out = (float*)d_out;
    float* out_ctx  = out;
    float* out_attn = out + BB * MEMD;

    cudaFuncSetAttribute(score_mma, cudaFuncAttributeMaxDynamicSharedMemorySize,
                         SMEM_DYN);

    zero_kernel<<<(BB * SS + 255) / 256, 256>>>(out_ctx);
    round_wm<<<(MEMD * ATT + 255) / 256, 256>>>(W_m);
    h_kernel<<<BB, 512>>>(hidden, W_h);
    {
        dim3 grid(ATT / BN, BB * SS / BM);
        score_mma<<<grid, 256, SMEM_DYN>>>(memory, coverage, W_c, v);
    }
    softmax_kernel<<<BB, 1024>>>(mem_pad, out_attn);
    {
        dim3 grid(BB, SS / 512);
        context_kernel<<<grid, 512>>>(memory, out_attn, out_ctx);
    }
}

// round 5
// speedup vs baseline: 3.2102x; 1.0335x over previous
#include <cuda_runtime.h>
#include <math.h>
#include <stdint.h>

#define BB   32
#define SS   4096
#define HID  512
#define MEMD 512
#define ATT  512

// ------------------------------- scratch -----------------------------------
__device__ float g_scores[BB * SS];
__device__ float g_h[BB * ATT];
// W_m permuted into per-thread fragment order, tf32(rna)-rounded.
// Layout (float4 units): [n0t(2)][stage(16)][i16(16)][chunk(128)] , i16 = ks*4+kh*2+jq
__device__ float g_Wp[2 * 16 * 16 * 128 * 4];

// ------------------------------- helpers -----------------------------------
__device__ __forceinline__ uint32_t smem_u32(const void* p) {
    return (uint32_t)__cvta_generic_to_shared(p);
}
__device__ __forceinline__ void cp16(uint32_t dst, const float* src) {
    asm volatile("cp.async.cg.shared.global [%0], [%1], 16;\n" :: "r"(dst), "l"(src));
}
__device__ __forceinline__ void cp_commit() { asm volatile("cp.async.commit_group;\n" ::: "memory"); }
template <int N>
__device__ __forceinline__ void cp_wait() {
    asm volatile("cp.async.wait_group %0;\n" :: "n"(N) : "memory");
}
__device__ __forceinline__ uint32_t f2tf32(float x) {
    uint32_t r;
    asm("cvt.rna.tf32.f32 %0, %1;" : "=r"(r) : "f"(x));
    return r;
}
__device__ __forceinline__ void mma_tf32(float* d, const uint32_t* a,
                                         uint32_t b0, uint32_t b1) {
    asm volatile(
        "mma.sync.aligned.m16n8k8.row.col.f32.tf32.tf32.f32 "
        "{%0,%1,%2,%3}, {%4,%5,%6,%7}, {%8,%9}, {%0,%1,%2,%3};"
        : "+f"(d[0]), "+f"(d[1]), "+f"(d[2]), "+f"(d[3])
        : "r"(a[0]), "r"(a[1]), "r"(a[2]), "r"(a[3]), "r"(b0), "r"(b1));
}
__device__ __forceinline__ float tanh_fast(float x) {
    float y; asm("tanh.approx.f32 %0, %1;" : "=f"(y) : "f"(x)); return y;
}

// ---------------------------------------------------------------------------
// zero: scores scratch + context output region
// ---------------------------------------------------------------------------
__global__ void zero_kernel(float* __restrict__ out_ctx) {
    int i = blockIdx.x * blockDim.x + threadIdx.x;
    if (i < BB * SS) g_scores[i] = 0.0f;
    if (i < BB * MEMD) out_ctx[i] = 0.0f;
}

// ---------------------------------------------------------------------------
// Build g_Wp: permuted, tf32(rna)-rounded W_m.
// Flat float index o -> (n0t, s, i16, chunk, e):
//   e = o&3; t4 = o>>2; chunk = t4 & 127; t = t4>>7; i16 = t&15; t>>=4;
//   s = t&15; n0t = t>>4.
//   ks = i16>>2; kh = (i16>>1)&1; jq = i16&1; j = jq*4 + e;
//   lane = chunk&31; warpN = chunk>>5; g = lane>>2; tg = lane&3;
//   k = s*32 + ks*8 + kh*4 + tg;
//   n = n0t*256 + warpN*64 + j*8 + g;
// ---------------------------------------------------------------------------
__global__ void permute_wm(const float* __restrict__ Wm) {
    int o = blockIdx.x * blockDim.x + threadIdx.x;
    if (o >= 2 * 16 * 16 * 128 * 4) return;
    int e = o & 3;
    int t4 = o >> 2;
    int chunk = t4 & 127;
    int t = t4 >> 7;
    int i16 = t & 15; t >>= 4;
    int s = t & 15;
    int n0t = t >> 4;
    int ks = i16 >> 2, kh = (i16 >> 1) & 1, jq = i16 & 1;
    int j = jq * 4 + e;
    int lane = chunk & 31, warpN = chunk >> 5;
    int g = lane >> 2, tg = lane & 3;
    int k = s * 32 + ks * 8 + kh * 4 + tg;
    int n = n0t * 256 + warpN * 64 + j * 8 + g;
    g_Wp[o] = __uint_as_float(f2tf32(Wm[k * ATT + n]));
}

// ---------------------------------------------------------------------------
// h[b][a] = hidden[b] . W_h[:,a]   grid=B, block=512
// ---------------------------------------------------------------------------
__global__ void h_kernel(const float* __restrict__ hidden,
                         const float* __restrict__ W_h) {
    __shared__ float sh[HID];
    int b = blockIdx.x;
    int a = threadIdx.x;
    sh[a] = hidden[b * HID + a];
    __syncthreads();
    float acc = 0.0f;
#pragma unroll 8
    for (int d = 0; d < HID; d++) acc += sh[d] * W_h[d * ATT + a];
    g_h[b * ATT + a] = acc;
}

// ---------------------------------------------------------------------------
// Score GEMM (tf32 mma.sync) fused with tanh/v epilogue.
// CTA tile 128(M) x 256(N), 8 warps (2M x 4N), warp tile 64x64.
// 3-stage cp.async pipeline. grid = (2 n-tiles, 1024 m-tiles).
// ---------------------------------------------------------------------------
#define BM 128
#define BN 256
#define BK 32
#define AST 36                    // A smem row stride (floats)
#define A_TILE (BM * AST)         // 4608 floats / stage
#define B_TILE (16 * 128 * 4)     // 8192 floats / stage ([i16][chunk] float4)
#define NSTAGE (MEMD / BK)        // 16
#define AUX_OFF (3 * A_TILE + 3 * B_TILE)
#define SMEM_DYN ((AUX_OFF + 3 * 512) * 4)

__global__ void __launch_bounds__(256, 1) score_mma(
    const float* __restrict__ Amem,
    const float* __restrict__ coverage,
    const float* __restrict__ Wc,
    const float* __restrict__ vvec) {

    extern __shared__ float dsm[];
    float* As_all = dsm;                       // 3 * A_TILE
    float* Bs_all = dsm + 3 * A_TILE;          // 3 * B_TILE
    float* sh_h   = dsm + AUX_OFF;             // 512 (absolute index)
    float* sh_wc  = sh_h + 512;
    float* sh_v   = sh_wc + 512;

    const int tid   = threadIdx.x;
    const int lane  = tid & 31;
    const int wid   = tid >> 5;
    const int warpM = wid & 1;      // 0..1
    const int warpN = wid >> 1;     // 0..3
    const int g     = lane >> 2;    // 0..7
    const int tg    = lane & 3;     // 0..3
    const int chunkB = warpN * 32 + lane;

    const int  n0t  = blockIdx.x;
    const int  n0   = n0t * BN;
    const long row0 = (long)blockIdx.y * BM;
    const int  b    = (int)(row0 >> 12);

    for (int i = tid; i < 512; i += 256) {
        sh_h[i]  = g_h[b * 512 + i];
        sh_wc[i] = Wc[i];
        sh_v[i]  = vvec[i];
    }

    float acc[4][8][4];
#pragma unroll
    for (int i = 0; i < 4; i++)
#pragma unroll
        for (int j = 0; j < 8; j++)
#pragma unroll
            for (int c = 0; c < 4; c++) acc[i][j][c] = 0.0f;

    const float* BsrcBase = g_Wp + (long)(n0t * 16) * (B_TILE);

    auto load_stage = [&](int s) {
        const int buf = s % 3;
        uint32_t Abu = smem_u32(As_all + buf * A_TILE);
        uint32_t Bbu = smem_u32(Bs_all + buf * B_TILE);
        const int k0 = s * BK;
        // A: 128 rows x 32 floats -> 1024 cp16
#pragma unroll
        for (int j = 0; j < 4; j++) {
            int c = tid + 256 * j;
            int r = c >> 3, c4 = c & 7;
            cp16(Abu + (r * AST + c4 * 4) * 4, Amem + (row0 + r) * 512 + k0 + c4 * 4);
        }
        // B: 2048 float4 in [i16][chunk] order -> 2048 cp16, thread does 8
        const float* Bsrc = BsrcBase + (long)s * B_TILE;
        {
            int chunk = tid & 127;
            int ibase = (tid >> 7) * 8;
#pragma unroll
            for (int jj = 0; jj < 8; jj++) {
                int f4 = (ibase + jj) * 128 + chunk;
                cp16(Bbu + f4 * 16, Bsrc + f4 * 4);
            }
        }
        cp_commit();
    };

    load_stage(0);
    load_stage(1);

    for (int s = 0; s < NSTAGE; s++) {
        if (s < NSTAGE - 1) cp_wait<1>(); else cp_wait<0>();
        __syncthreads();
        if (s + 2 < NSTAGE) load_stage(s + 2);

        const int buf = s % 3;
        const float*  Ab = As_all + buf * A_TILE;
        const float4* B4 = (const float4*)(Bs_all + buf * B_TILE);

#pragma unroll
        for (int ks = 0; ks < 4; ks++) {
            // A fragments (raw fp32 bits; HW reads tf32 high bits)
            uint32_t af[4][4];
#pragma unroll
            for (int i = 0; i < 4; i++) {
                int r = warpM * 64 + i * 16 + g;
                int c = ks * 8 + tg;
                af[i][0] = __float_as_uint(Ab[r * AST + c]);
                af[i][1] = __float_as_uint(Ab[(r + 8) * AST + c]);
                af[i][2] = __float_as_uint(Ab[r * AST + c + 4]);
                af[i][3] = __float_as_uint(Ab[(r + 8) * AST + c + 4]);
            }
            // B fragments: 4x LDS.128 from permuted layout
            float4 bA = B4[(ks * 4 + 0) * 128 + chunkB];  // kh0, j0-3
            float4 bB = B4[(ks * 4 + 1) * 128 + chunkB];  // kh0, j4-7
            float4 bC = B4[(ks * 4 + 2) * 128 + chunkB];  // kh1, j0-3
            float4 bD = B4[(ks * 4 + 3) * 128 + chunkB];  // kh1, j4-7
            uint32_t bu0[8], bu1[8];
            bu0[0] = __float_as_uint(bA.x); bu0[1] = __float_as_uint(bA.y);
            bu0[2] = __float_as_uint(bA.z); bu0[3] = __float_as_uint(bA.w);
            bu0[4] = __float_as_uint(bB.x); bu0[5] = __float_as_uint(bB.y);
            bu0[6] = __float_as_uint(bB.z); bu0[7] = __float_as_uint(bB.w);
            bu1[0] = __float_as_uint(bC.x); bu1[1] = __float_as_uint(bC.y);
            bu1[2] = __float_as_uint(bC.z); bu1[3] = __float_as_uint(bC.w);
            bu1[4] = __float_as_uint(bD.x); bu1[5] = __float_as_uint(bD.y);
            bu1[6] = __float_as_uint(bD.z); bu1[7] = __float_as_uint(bD.w);
#pragma unroll
            for (int i = 0; i < 4; i++)
#pragma unroll
                for (int j = 0; j < 8; j++)
                    mma_tf32(acc[i][j], af[i], bu0[j], bu1[j]);
        }
    }

    // ---- epilogue: tanh + v-dot partial over this CTA's 256 n-cols ----
#pragma unroll
    for (int i = 0; i < 4; i++) {
        const int r_lo = warpM * 64 + i * 16 + g;
        const int r_hi = r_lo + 8;
        const float cov_lo = coverage[row0 + r_lo];
        const float cov_hi = coverage[row0 + r_hi];
        float p_lo = 0.0f, p_hi = 0.0f;
#pragma unroll
        for (int j = 0; j < 8; j++) {
            const int nb = n0 + warpN * 64 + j * 8 + tg * 2;  // absolute col
            const float h0 = sh_h[nb + 0], h1 = sh_h[nb + 1];
            const float w0 = sh_wc[nb + 0], w1 = sh_wc[nb + 1];
            const float v0 = sh_v[nb + 0], v1 = sh_v[nb + 1];
            p_lo += tanh_fast(acc[i][j][0] + h0 + cov_lo * w0) * v0;
            p_lo += tanh_fast(acc[i][j][1] + h1 + cov_lo * w1) * v1;
            p_hi += tanh_fast(acc[i][j][2] + h0 + cov_hi * w0) * v0;
            p_hi += tanh_fast(acc[i][j][3] + h1 + cov_hi * w1) * v1;
        }
        p_lo += __shfl_xor_sync(0xffffffffu, p_lo, 1);
        p_lo += __shfl_xor_sync(0xffffffffu, p_lo, 2);
        p_hi += __shfl_xor_sync(0xffffffffu, p_hi, 1);
        p_hi += __shfl_xor_sync(0xffffffffu, p_hi, 2);
        if (tg == 0) {
            atomicAdd(&g_scores[row0 + r_lo], p_lo);
            atomicAdd(&g_scores[row0 + r_hi], p_hi);
        }
    }
}

// ---------------------------------------------------------------------------
// Softmax over S per batch (with pad mask). grid=B, block=1024.
// ---------------------------------------------------------------------------
__global__ void softmax_kernel(const unsigned char* __restrict__ pad,
                               float* __restrict__ attn) {
    __shared__ float red[1024];
    const int b = blockIdx.x;
    const int tid = threadIdx.x;

    float mx = -INFINITY;
    for (int s = tid; s < SS; s += 1024) {
        float sc = pad[b * SS + s] ? -INFINITY : g_scores[b * SS + s];
        mx = fmaxf(mx, sc);
    }
    red[tid] = mx;
    __syncthreads();
    for (int off = 512; off > 0; off >>= 1) {
        if (tid < off) red[tid] = fmaxf(red[tid], red[tid + off]);
        __syncthreads();
    }
    mx = red[0];
    __syncthreads();

    float sum = 0.0f;
    for (int s = tid; s < SS; s += 1024) {
        float sc = pad[b * SS + s] ? -INFINITY : g_scores[b * SS + s];
        float e = expf(sc - mx);
        attn[b * SS + s] = e;
        sum += e;
    }
    red[tid] = sum;
    __syncthreads();
    for (int off = 512; off > 0; off >>= 1) {
        if (tid < off) red[tid] += red[tid + off];
        __syncthreads();
    }
    float inv = 1.0f / red[0];
    for (int s = tid; s < SS; s += 1024) attn[b * SS + s] *= inv;
}

// ---------------------------------------------------------------------------
// context[b][d] = sum_s attn[b][s] * memory[b][s][d]. grid=(B,16), block=512.
// ---------------------------------------------------------------------------
__global__ void context_kernel(const float* __restrict__ memory,
                               const float* __restrict__ attn,
                               float* __restrict__ ctx) {
    __shared__ float w[256];
    const int b = blockIdx.x;
    const int s0 = blockIdx.y * 256;
    const int d = threadIdx.x;

    if (d < 256) w[d] = attn[b * SS + s0 + d];
    __syncthreads();

    float acc = 0.0f;
    const float* mbase = memory + ((long)b * SS + s0) * MEMD + d;
#pragma unroll 4
    for (int s = 0; s < 256; s++) acc += w[s] * mbase[(long)s * MEMD];
    atomicAdd(&ctx[b * MEMD + d], acc);
}

// ---------------------------------------------------------------------------
// Launch.  Inputs (metadata order):
//   0 hidden | 1 memory | 2 mem_pad | 3 coverage | 4 W_h | 5 W_m | 6 W_c | 7 v
// Output: [context (B*MEM) | attn (B*S)] f32
// ---------------------------------------------------------------------------
extern "C" void kernel_launch(void* const* d_in, const int* in_sizes, int n_in,
                              void* d_out, int out_size) {
    const float* hidden   = (const float*)d_in[0];
    const float* memory   = (const float*)d_in[1];
    const unsigned char* mem_pad = (const unsigned char*)d_in[2];
    const float* coverage = (const float*)d_in[3];
    const float* W_h      = (const float*)d_in[4];
    const float* W_m      = (const float*)d_in[5];
    const float* W_c      = (const float*)d_in[6];
    const float* v        = (const float*)d_in[7];

    float* out = (float*)d_out;
    float* out_ctx  = out;
    float* out_attn = out + BB * MEMD;

    cudaFuncSetAttribute(score_mma, cudaFuncAttributeMaxDynamicSharedMemorySize,
                         SMEM_DYN);

    zero_kernel<<<(BB * SS + 255) / 256, 256>>>(out_ctx);
    permute_wm<<<(2 * 16 * 16 * 128 * 4 + 255) / 256, 256>>>(W_m);
    h_kernel<<<BB, 512>>>(hidden, W_h);
    {
        dim3 grid(ATT / BN, BB * SS / BM);
        score_mma<<<grid, 256, SMEM_DYN>>>(memory, coverage, W_c, v);
    }
    softmax_kernel<<<BB, 1024>>>(mem_pad, out_attn);
    {
        dim3 grid(BB, SS / 256);
        context_kernel<<<grid, 512>>>(memory, out_attn, out_ctx);
    }
}

// round 6
// speedup vs baseline: 3.3446x; 1.0419x over previous
#include <cuda_runtime.h>
#include <math.h>
#include <stdint.h>

#define BB   32
#define SS   4096
#define HID  512
#define MEMD 512
#define ATT  512

// ------------------------------- scratch -----------------------------------
__device__ float g_scores[BB * SS];
__device__ float g_h[BB * ATT];
// W_m permuted into per-thread fragment order, tf32(rna)-rounded.
// Layout (float4 units): [n0t(2)][stage(16)][i16(16)][chunk(128)], i16 = ks*4+kh*2+jq
__device__ float g_Wp[2 * 16 * 16 * 128 * 4];

// ------------------------------- helpers -----------------------------------
__device__ __forceinline__ uint32_t smem_u32(const void* p) {
    return (uint32_t)__cvta_generic_to_shared(p);
}
__device__ __forceinline__ void cp16(uint32_t dst, const float* src) {
    asm volatile("cp.async.cg.shared.global [%0], [%1], 16;\n" :: "r"(dst), "l"(src));
}
__device__ __forceinline__ void cp_commit() { asm volatile("cp.async.commit_group;\n" ::: "memory"); }
template <int N>
__device__ __forceinline__ void cp_wait() {
    asm volatile("cp.async.wait_group %0;\n" :: "n"(N) : "memory");
}
__device__ __forceinline__ uint32_t f2tf32(float x) {
    uint32_t r;
    asm("cvt.rna.tf32.f32 %0, %1;" : "=r"(r) : "f"(x));
    return r;
}
__device__ __forceinline__ void mma_tf32(float* d, const uint32_t* a,
                                         uint32_t b0, uint32_t b1) {
    asm volatile(
        "mma.sync.aligned.m16n8k8.row.col.f32.tf32.tf32.f32 "
        "{%0,%1,%2,%3}, {%4,%5,%6,%7}, {%8,%9}, {%0,%1,%2,%3};"
        : "+f"(d[0]), "+f"(d[1]), "+f"(d[2]), "+f"(d[3])
        : "r"(a[0]), "r"(a[1]), "r"(a[2]), "r"(a[3]), "r"(b0), "r"(b1));
}
__device__ __forceinline__ float tanh_fast(float x) {
    float y; asm("tanh.approx.f32 %0, %1;" : "=f"(y) : "f"(x)); return y;
}

// ---------------------------------------------------------------------------
// zero: scores scratch + context output region
// ---------------------------------------------------------------------------
__global__ void zero_kernel(float* __restrict__ out_ctx) {
    int i = blockIdx.x * blockDim.x + threadIdx.x;
    if (i < BB * SS) g_scores[i] = 0.0f;
    if (i < BB * MEMD) out_ctx[i] = 0.0f;
}

// ---------------------------------------------------------------------------
// Build g_Wp: permuted, tf32(rna)-rounded W_m. (same as R5 — warpN semantics)
// ---------------------------------------------------------------------------
__global__ void permute_wm(const float* __restrict__ Wm) {
    int o = blockIdx.x * blockDim.x + threadIdx.x;
    if (o >= 2 * 16 * 16 * 128 * 4) return;
    int e = o & 3;
    int t4 = o >> 2;
    int chunk = t4 & 127;
    int t = t4 >> 7;
    int i16 = t & 15; t >>= 4;
    int s = t & 15;
    int n0t = t >> 4;
    int ks = i16 >> 2, kh = (i16 >> 1) & 1, jq = i16 & 1;
    int j = jq * 4 + e;
    int lane = chunk & 31, warpN = chunk >> 5;
    int g = lane >> 2, tg = lane & 3;
    int k = s * 32 + ks * 8 + kh * 4 + tg;
    int n = n0t * 256 + warpN * 64 + j * 8 + g;
    g_Wp[o] = __uint_as_float(f2tf32(Wm[k * ATT + n]));
}

// ---------------------------------------------------------------------------
// h[b][a] = hidden[b] . W_h[:,a]   grid=B, block=512
// ---------------------------------------------------------------------------
__global__ void h_kernel(const float* __restrict__ hidden,
                         const float* __restrict__ W_h) {
    __shared__ float sh[HID];
    int b = blockIdx.x;
    int a = threadIdx.x;
    sh[a] = hidden[b * HID + a];
    __syncthreads();
    float acc = 0.0f;
#pragma unroll 8
    for (int d = 0; d < HID; d++) acc += sh[d] * W_h[d * ATT + a];
    g_h[b * ATT + a] = acc;
}

// ---------------------------------------------------------------------------
// Score GEMM (tf32 mma.sync) fused with tanh/v epilogue.
// CTA tile 128(M) x 256(N), 16 warps (4M x 4N), warp tile 32x64, 512 threads.
// 3-stage cp.async pipeline. grid = (2 n-tiles, 1024 m-tiles).
// ---------------------------------------------------------------------------
#define BM 128
#define BN 256
#define BK 32
#define AST 36                    // A smem row stride (floats)
#define A_TILE (BM * AST)         // 4608 floats / stage
#define B_TILE (16 * 128 * 4)     // 8192 floats / stage ([i16][chunk] float4)
#define NSTAGE (MEMD / BK)        // 16
#define AUX_OFF (3 * A_TILE + 3 * B_TILE)
#define SMEM_DYN ((AUX_OFF + 3 * 512) * 4)

__global__ void __launch_bounds__(512, 1) score_mma(
    const float* __restrict__ Amem,
    const float* __restrict__ coverage,
    const float* __restrict__ Wc,
    const float* __restrict__ vvec) {

    extern __shared__ float dsm[];
    float* As_all = dsm;                       // 3 * A_TILE
    float* Bs_all = dsm + 3 * A_TILE;          // 3 * B_TILE
    float* sh_h   = dsm + AUX_OFF;             // 512 (absolute index)
    float* sh_wc  = sh_h + 512;
    float* sh_v   = sh_wc + 512;

    const int tid   = threadIdx.x;
    const int lane  = tid & 31;
    const int wid   = tid >> 5;     // 0..15
    const int warpN = wid & 3;      // 0..3
    const int warpM = wid >> 2;     // 0..3
    const int g     = lane >> 2;    // 0..7
    const int tg    = lane & 3;     // 0..3
    const int chunkB = warpN * 32 + lane;

    const int  n0t  = blockIdx.x;
    const int  n0   = n0t * BN;
    const long row0 = (long)blockIdx.y * BM;
    const int  b    = (int)(row0 >> 12);

    if (tid < 512) {
        sh_h[tid]  = g_h[b * 512 + tid];
        sh_wc[tid] = Wc[tid];
        sh_v[tid]  = vvec[tid];
    }

    float acc[2][8][4];
#pragma unroll
    for (int i = 0; i < 2; i++)
#pragma unroll
        for (int j = 0; j < 8; j++)
#pragma unroll
            for (int c = 0; c < 4; c++) acc[i][j][c] = 0.0f;

    const float* BsrcBase = g_Wp + (long)(n0t * 16) * B_TILE;

    auto load_stage = [&](int s) {
        const int buf = s % 3;
        uint32_t Abu = smem_u32(As_all + buf * A_TILE);
        uint32_t Bbu = smem_u32(Bs_all + buf * B_TILE);
        const int k0 = s * BK;
        // A: 128 rows x 8 float4 = 1024 cp16 over 512 threads -> 2 each
#pragma unroll
        for (int j = 0; j < 2; j++) {
            int c = tid + 512 * j;
            int r = c >> 3, c4 = c & 7;
            cp16(Abu + (r * AST + c4 * 4) * 4, Amem + (row0 + r) * 512 + k0 + c4 * 4);
        }
        // B: 2048 float4 -> 4 each (coalesced: consecutive tid = consecutive chunk)
        const float* Bsrc = BsrcBase + (long)s * B_TILE;
        {
            int chunk = tid & 127;
            int ibase = (tid >> 7) * 4;
#pragma unroll
            for (int jj = 0; jj < 4; jj++) {
                int f4 = (ibase + jj) * 128 + chunk;
                cp16(Bbu + f4 * 16, Bsrc + f4 * 4);
            }
        }
        cp_commit();
    };

    load_stage(0);
    load_stage(1);

    for (int s = 0; s < NSTAGE; s++) {
        if (s < NSTAGE - 1) cp_wait<1>(); else cp_wait<0>();
        __syncthreads();
        if (s + 2 < NSTAGE) load_stage(s + 2);

        const int buf = s % 3;
        const float*  Ab = As_all + buf * A_TILE;
        const float4* B4 = (const float4*)(Bs_all + buf * B_TILE);

#pragma unroll
        for (int ks = 0; ks < 4; ks++) {
            // A fragments (raw fp32 bits; HW reads tf32 high bits)
            uint32_t af[2][4];
#pragma unroll
            for (int i = 0; i < 2; i++) {
                int r = warpM * 32 + i * 16 + g;
                int c = ks * 8 + tg;
                af[i][0] = __float_as_uint(Ab[r * AST + c]);
                af[i][1] = __float_as_uint(Ab[(r + 8) * AST + c]);
                af[i][2] = __float_as_uint(Ab[r * AST + c + 4]);
                af[i][3] = __float_as_uint(Ab[(r + 8) * AST + c + 4]);
            }
            // B fragments: 4x LDS.128 from permuted layout
            float4 bA = B4[(ks * 4 + 0) * 128 + chunkB];  // kh0, j0-3
            float4 bB = B4[(ks * 4 + 1) * 128 + chunkB];  // kh0, j4-7
            float4 bC = B4[(ks * 4 + 2) * 128 + chunkB];  // kh1, j0-3
            float4 bD = B4[(ks * 4 + 3) * 128 + chunkB];  // kh1, j4-7
            uint32_t bu0[8], bu1[8];
            bu0[0] = __float_as_uint(bA.x); bu0[1] = __float_as_uint(bA.y);
            bu0[2] = __float_as_uint(bA.z); bu0[3] = __float_as_uint(bA.w);
            bu0[4] = __float_as_uint(bB.x); bu0[5] = __float_as_uint(bB.y);
            bu0[6] = __float_as_uint(bB.z); bu0[7] = __float_as_uint(bB.w);
            bu1[0] = __float_as_uint(bC.x); bu1[1] = __float_as_uint(bC.y);
            bu1[2] = __float_as_uint(bC.z); bu1[3] = __float_as_uint(bC.w);
            bu1[4] = __float_as_uint(bD.x); bu1[5] = __float_as_uint(bD.y);
            bu1[6] = __float_as_uint(bD.z); bu1[7] = __float_as_uint(bD.w);
#pragma unroll
            for (int i = 0; i < 2; i++)
#pragma unroll
                for (int j = 0; j < 8; j++)
                    mma_tf32(acc[i][j], af[i], bu0[j], bu1[j]);
        }
    }

    // ---- epilogue: tanh + v-dot partial over this CTA's 256 n-cols ----
#pragma unroll
    for (int i = 0; i < 2; i++) {
        const int r_lo = warpM * 32 + i * 16 + g;
        const int r_hi = r_lo + 8;
        const float cov_lo = coverage[row0 + r_lo];
        const float cov_hi = coverage[row0 + r_hi];
        float p_lo = 0.0f, p_hi = 0.0f;
#pragma unroll
        for (int j = 0; j < 8; j++) {
            const int nb = n0 + warpN * 64 + j * 8 + tg * 2;  // absolute col
            const float h0 = sh_h[nb + 0], h1 = sh_h[nb + 1];
            const float w0 = sh_wc[nb + 0], w1 = sh_wc[nb + 1];
            const float v0 = sh_v[nb + 0], v1 = sh_v[nb + 1];
            p_lo += tanh_fast(acc[i][j][0] + h0 + cov_lo * w0) * v0;
            p_lo += tanh_fast(acc[i][j][1] + h1 + cov_lo * w1) * v1;
            p_hi += tanh_fast(acc[i][j][2] + h0 + cov_hi * w0) * v0;
            p_hi += tanh_fast(acc[i][j][3] + h1 + cov_hi * w1) * v1;
        }
        p_lo += __shfl_xor_sync(0xffffffffu, p_lo, 1);
        p_lo += __shfl_xor_sync(0xffffffffu, p_lo, 2);
        p_hi += __shfl_xor_sync(0xffffffffu, p_hi, 1);
        p_hi += __shfl_xor_sync(0xffffffffu, p_hi, 2);
        if (tg == 0) {
            atomicAdd(&g_scores[row0 + r_lo], p_lo);
            atomicAdd(&g_scores[row0 + r_hi], p_hi);
        }
    }
}

// ---------------------------------------------------------------------------
// Softmax over S per batch (with pad mask). grid=B, block=1024.
// ---------------------------------------------------------------------------
__global__ void softmax_kernel(const unsigned char* __restrict__ pad,
                               float* __restrict__ attn) {
    __shared__ float red[1024];
    const int b = blockIdx.x;
    const int tid = threadIdx.x;

    float mx = -INFINITY;
    for (int s = tid; s < SS; s += 1024) {
        float sc = pad[b * SS + s] ? -INFINITY : g_scores[b * SS + s];
        mx = fmaxf(mx, sc);
    }
    red[tid] = mx;
    __syncthreads();
    for (int off = 512; off > 0; off >>= 1) {
        if (tid < off) red[tid] = fmaxf(red[tid], red[tid + off]);
        __syncthreads();
    }
    mx = red[0];
    __syncthreads();

    float sum = 0.0f;
    for (int s = tid; s < SS; s += 1024) {
        float sc = pad[b * SS + s] ? -INFINITY : g_scores[b * SS + s];
        float e = expf(sc - mx);
        attn[b * SS + s] = e;
        sum += e;
    }
    red[tid] = sum;
    __syncthreads();
    for (int off = 512; off > 0; off >>= 1) {
        if (tid < off) red[tid] += red[tid + off];
        __syncthreads();
    }
    float inv = 1.0f / red[0];
    for (int s = tid; s < SS; s += 1024) attn[b * SS + s] *= inv;
}

// ---------------------------------------------------------------------------
// context[b][d] = sum_s attn[b][s] * memory[b][s][d]. grid=(B,32), block=512.
// ---------------------------------------------------------------------------
__global__ void context_kernel(const float* __restrict__ memory,
                               const float* __restrict__ attn,
                               float* __restrict__ ctx) {
    __shared__ float w[128];
    const int b = blockIdx.x;
    const int s0 = blockIdx.y * 128;
    const int d = threadIdx.x;

    if (d < 128) w[d] = attn[b * SS + s0 + d];
    __syncthreads();

    float acc = 0.0f;
    const float* mbase = memory + ((long)b * SS + s0) * MEMD + d;
#pragma unroll 4
    for (int s = 0; s < 128; s++) acc += w[s] * mbase[(long)s * MEMD];
    atomicAdd(&ctx[b * MEMD + d], acc);
}

// ---------------------------------------------------------------------------
// Launch.  Inputs (metadata order):
//   0 hidden | 1 memory | 2 mem_pad | 3 coverage | 4 W_h | 5 W_m | 6 W_c | 7 v
// Output: [context (B*MEM) | attn (B*S)] f32
// ---------------------------------------------------------------------------
extern "C" void kernel_launch(void* const* d_in, const int* in_sizes, int n_in,
                              void* d_out, int out_size) {
    const float* hidden   = (const float*)d_in[0];
    const float* memory   = (const float*)d_in[1];
    const unsigned char* mem_pad = (const unsigned char*)d_in[2];
    const float* coverage = (const float*)d_in[3];
    const float* W_h      = (const float*)d_in[4];
    const float* W_m      = (const float*)d_in[5];
    const float* W_c      = (const float*)d_in[6];
    const float* v        = (const float*)d_in[7];

    float* out = (float*)d_out;
    float* out_ctx  = out;
    float* out_attn = out + BB * MEMD;

    cudaFuncSetAttribute(score_mma, cudaFuncAttributeMaxDynamicSharedMemorySize,
                         SMEM_DYN);

    zero_kernel<<<(BB * SS + 255) / 256, 256>>>(out_ctx);
    permute_wm<<<(2 * 16 * 16 * 128 * 4 + 255) / 256, 256>>>(W_m);
    h_kernel<<<BB, 512>>>(hidden, W_h);
    {
        dim3 grid(ATT / BN, BB * SS / BM);
        score_mma<<<grid, 512, SMEM_DYN>>>(memory, coverage, W_c, v);
    }
    softmax_kernel<<<BB, 1024>>>(mem_pad, out_attn);
    {
        dim3 grid(BB, SS / 128);
        context_kernel<<<grid, 512>>>(memory, out_attn, out_ctx);
    }
}

// round 7
// speedup vs baseline: 4.0125x; 1.1997x over previous
#include <cuda_runtime.h>
#include <cuda_fp16.h>
#include <math.h>
#include <stdint.h>

#define BB   32
#define SS   4096
#define HID  512
#define MEMD 512
#define ATT  512

// ------------------------------- scratch -----------------------------------
__device__ float g_scores[BB * SS];
__device__ float g_h[BB * ATT];
// W_m permuted into per-thread fp16 fragment order for m16n8k16.
// uint (half2) layout: [n0t(2)][stage(16)][i8(8)][chunk(128)][e(4)]
//   i8 = kk*4 + kb*2 + jq ; j = jq*4 + e ; chunk = warpN*32 + lane
//   half2 = { W[k][n], W[k+1][n] },  k = s*32 + kk*16 + kb*8 + 2*tg
//   n = n0t*256 + warpN*64 + j*8 + g
__device__ unsigned int g_Wp16[2 * 16 * 8 * 128 * 4];

// ------------------------------- helpers -----------------------------------
__device__ __forceinline__ uint32_t smem_u32(const void* p) {
    return (uint32_t)__cvta_generic_to_shared(p);
}
__device__ __forceinline__ void cp16(uint32_t dst, const void* src) {
    asm volatile("cp.async.cg.shared.global [%0], [%1], 16;\n" :: "r"(dst), "l"(src));
}
__device__ __forceinline__ void cp_commit() { asm volatile("cp.async.commit_group;\n" ::: "memory"); }
template <int N>
__device__ __forceinline__ void cp_wait() {
    asm volatile("cp.async.wait_group %0;\n" :: "n"(N) : "memory");
}
// pack float2 {x=k_even, y=k_odd} -> f16x2 reg (lo = x)
__device__ __forceinline__ uint32_t pack_f16x2(float2 p) {
    uint32_t d;
    asm("cvt.rn.f16x2.f32 %0, %1, %2;" : "=r"(d) : "f"(p.y), "f"(p.x));
    return d;
}
__device__ __forceinline__ void mma_f16(float* d, uint32_t a0, uint32_t a1,
                                        uint32_t a2, uint32_t a3,
                                        uint32_t b0, uint32_t b1) {
    asm volatile(
        "mma.sync.aligned.m16n8k16.row.col.f32.f16.f16.f32 "
        "{%0,%1,%2,%3}, {%4,%5,%6,%7}, {%8,%9}, {%0,%1,%2,%3};"
        : "+f"(d[0]), "+f"(d[1]), "+f"(d[2]), "+f"(d[3])
        : "r"(a0), "r"(a1), "r"(a2), "r"(a3), "r"(b0), "r"(b1));
}
__device__ __forceinline__ float tanh_fast(float x) {
    float y; asm("tanh.approx.f32 %0, %1;" : "=f"(y) : "f"(x)); return y;
}

// ---------------------------------------------------------------------------
// zero: scores scratch + context output region
// ---------------------------------------------------------------------------
__global__ void zero_kernel(float* __restrict__ out_ctx) {
    int i = blockIdx.x * blockDim.x + threadIdx.x;
    if (i < BB * SS) g_scores[i] = 0.0f;
    if (i < BB * MEMD) out_ctx[i] = 0.0f;
}

// ---------------------------------------------------------------------------
// Build g_Wp16 (fp16 permuted fragment layout). One thread per half2.
// ---------------------------------------------------------------------------
__global__ void permute_wm16(const float* __restrict__ Wm) {
    int o = blockIdx.x * blockDim.x + threadIdx.x;
    if (o >= 2 * 16 * 8 * 128 * 4) return;
    int e     = o & 3;
    int chunk = (o >> 2) & 127;
    int i8    = (o >> 9) & 7;
    int s     = (o >> 12) & 15;
    int n0t   = o >> 16;
    int kk = i8 >> 2, kb = (i8 >> 1) & 1, jq = i8 & 1;
    int j = jq * 4 + e;
    int lane = chunk & 31, warpN = chunk >> 5;
    int g = lane >> 2, tg = lane & 3;
    int k = s * 32 + kk * 16 + kb * 8 + 2 * tg;
    int n = n0t * 256 + warpN * 64 + j * 8 + g;
    __half2 h = __floats2half2_rn(Wm[k * ATT + n], Wm[(k + 1) * ATT + n]);
    g_Wp16[o] = *reinterpret_cast<unsigned int*>(&h);
}

// ---------------------------------------------------------------------------
// h[b][a] = hidden[b] . W_h[:,a]   grid=B, block=512
// ---------------------------------------------------------------------------
__global__ void h_kernel(const float* __restrict__ hidden,
                         const float* __restrict__ W_h) {
    __shared__ float sh[HID];
    int b = blockIdx.x;
    int a = threadIdx.x;
    sh[a] = hidden[b * HID + a];
    __syncthreads();
    float acc = 0.0f;
#pragma unroll 8
    for (int d = 0; d < HID; d++) acc += sh[d] * W_h[d * ATT + a];
    g_h[b * ATT + a] = acc;
}

// ---------------------------------------------------------------------------
// Score GEMM (fp16 m16n8k16 mma.sync, fp32 accumulate) + tanh/v epilogue.
// CTA tile 128(M) x 256(N), 16 warps (4M x 4N), warp tile 32x64, 512 threads.
// A kept fp32 in smem (converted to fp16 in registers); B pre-permuted fp16.
// 3-stage cp.async pipeline. grid = (2 n-tiles, 1024 m-tiles).
// ---------------------------------------------------------------------------
#define BM 128
#define BN 256
#define BK 32
#define AST 36                        // A smem row stride (fp32 words)
#define A_TILE (BM * AST)             // 4608 floats / stage
#define B_TILE_U (8 * 128 * 4)        // 4096 uints (half2) / stage = 16KB
#define NSTAGE (MEMD / BK)            // 16
#define AUX_OFF (3 * A_TILE + 3 * B_TILE_U)
#define SMEM_DYN ((AUX_OFF + 3 * 512) * 4)

__global__ void __launch_bounds__(512, 1) score_mma(
    const float* __restrict__ Amem,
    const float* __restrict__ coverage,
    const float* __restrict__ Wc,
    const float* __restrict__ vvec) {

    extern __shared__ float dsm[];
    float* As_all = dsm;                                   // 3 * A_TILE fp32
    unsigned int* Bs_all = (unsigned int*)(dsm + 3 * A_TILE); // 3 * B_TILE_U
    float* sh_h   = dsm + AUX_OFF;                         // 512 (absolute)
    float* sh_wc  = sh_h + 512;
    float* sh_v   = sh_wc + 512;

    const int tid   = threadIdx.x;
    const int lane  = tid & 31;
    const int wid   = tid >> 5;     // 0..15
    const int warpN = wid & 3;      // 0..3
    const int warpM = wid >> 2;     // 0..3
    const int g     = lane >> 2;    // 0..7
    const int tg    = lane & 3;     // 0..3
    const int chunkB = warpN * 32 + lane;

    const int  n0t  = blockIdx.x;
    const int  n0   = n0t * BN;
    const long row0 = (long)blockIdx.y * BM;
    const int  b    = (int)(row0 >> 12);

    if (tid < 512) {
        sh_h[tid]  = g_h[b * 512 + tid];
        sh_wc[tid] = Wc[tid];
        sh_v[tid]  = vvec[tid];
    }

    float acc[2][8][4];
#pragma unroll
    for (int i = 0; i < 2; i++)
#pragma unroll
        for (int j = 0; j < 8; j++)
#pragma unroll
            for (int c = 0; c < 4; c++) acc[i][j][c] = 0.0f;

    const unsigned int* BsrcBase = g_Wp16 + (long)n0t * 16 * B_TILE_U;

    auto load_stage = [&](int s) {
        const int buf = s % 3;
        uint32_t Abu = smem_u32(As_all + buf * A_TILE);
        uint32_t Bbu = smem_u32(Bs_all + buf * B_TILE_U);
        const int k0 = s * BK;
        // A: 128 rows x 8 float4 = 1024 cp16 over 512 threads -> 2 each
#pragma unroll
        for (int j = 0; j < 2; j++) {
            int c = tid + 512 * j;
            int r = c >> 3, c4 = c & 7;
            cp16(Abu + (r * AST + c4 * 4) * 4, Amem + (row0 + r) * 512 + k0 + c4 * 4);
        }
        // B: 1024 uint4 -> 2 each (coalesced)
        const unsigned int* Bsrc = BsrcBase + (long)s * B_TILE_U;
        {
            int chunk = tid & 127;
            int ibase = (tid >> 7) * 2;
#pragma unroll
            for (int jj = 0; jj < 2; jj++) {
                int u4 = (ibase + jj) * 128 + chunk;   // uint4 index
                cp16(Bbu + u4 * 16, Bsrc + u4 * 4);
            }
        }
        cp_commit();
    };

    load_stage(0);
    load_stage(1);

    for (int s = 0; s < NSTAGE; s++) {
        if (s < NSTAGE - 1) cp_wait<1>(); else cp_wait<0>();
        __syncthreads();
        if (s + 2 < NSTAGE) load_stage(s + 2);

        const int buf = s % 3;
        const float* Ab = As_all + buf * A_TILE;
        const uint4* B4 = (const uint4*)(Bs_all + buf * B_TILE_U);

#pragma unroll
        for (int kk = 0; kk < 2; kk++) {
            // B fragments: 4x LDS.128
            uint4 q0 = B4[(kk * 4 + 0) * 128 + chunkB];  // b0, j0-3
            uint4 q1 = B4[(kk * 4 + 1) * 128 + chunkB];  // b0, j4-7
            uint4 q2 = B4[(kk * 4 + 2) * 128 + chunkB];  // b1, j0-3
            uint4 q3 = B4[(kk * 4 + 3) * 128 + chunkB];  // b1, j4-7
            uint32_t b0[8] = {q0.x, q0.y, q0.z, q0.w, q1.x, q1.y, q1.z, q1.w};
            uint32_t b1[8] = {q2.x, q2.y, q2.z, q2.w, q3.x, q3.y, q3.z, q3.w};

#pragma unroll
            for (int i = 0; i < 2; i++) {
                const int r = warpM * 32 + i * 16 + g;
                const int kbase = kk * 16 + 2 * tg;
                float2 p0 = *(const float2*)(Ab + r * AST + kbase);
                float2 p1 = *(const float2*)(Ab + (r + 8) * AST + kbase);
                float2 p2 = *(const float2*)(Ab + r * AST + kbase + 8);
                float2 p3 = *(const float2*)(Ab + (r + 8) * AST + kbase + 8);
                uint32_t a0 = pack_f16x2(p0);
                uint32_t a1 = pack_f16x2(p1);
                uint32_t a2 = pack_f16x2(p2);
                uint32_t a3 = pack_f16x2(p3);
#pragma unroll
                for (int j = 0; j < 8; j++)
                    mma_f16(acc[i][j], a0, a1, a2, a3, b0[j], b1[j]);
            }
        }
    }

    // ---- epilogue: tanh + v-dot partial over this CTA's 256 n-cols ----
#pragma unroll
    for (int i = 0; i < 2; i++) {
        const int r_lo = warpM * 32 + i * 16 + g;
        const int r_hi = r_lo + 8;
        const float cov_lo = coverage[row0 + r_lo];
        const float cov_hi = coverage[row0 + r_hi];
        float p_lo = 0.0f, p_hi = 0.0f;
#pragma unroll
        for (int j = 0; j < 8; j++) {
            const int nb = n0 + warpN * 64 + j * 8 + tg * 2;  // absolute col
            const float h0 = sh_h[nb + 0], h1 = sh_h[nb + 1];
            const float w0 = sh_wc[nb + 0], w1 = sh_wc[nb + 1];
            const float v0 = sh_v[nb + 0], v1 = sh_v[nb + 1];
            p_lo += tanh_fast(acc[i][j][0] + h0 + cov_lo * w0) * v0;
            p_lo += tanh_fast(acc[i][j][1] + h1 + cov_lo * w1) * v1;
            p_hi += tanh_fast(acc[i][j][2] + h0 + cov_hi * w0) * v0;
            p_hi += tanh_fast(acc[i][j][3] + h1 + cov_hi * w1) * v1;
        }
        p_lo += __shfl_xor_sync(0xffffffffu, p_lo, 1);
        p_lo += __shfl_xor_sync(0xffffffffu, p_lo, 2);
        p_hi += __shfl_xor_sync(0xffffffffu, p_hi, 1);
        p_hi += __shfl_xor_sync(0xffffffffu, p_hi, 2);
        if (tg == 0) {
            atomicAdd(&g_scores[row0 + r_lo], p_lo);
            atomicAdd(&g_scores[row0 + r_hi], p_hi);
        }
    }
}

// ---------------------------------------------------------------------------
// Softmax over S per batch (with pad mask). grid=B, block=1024.
// ---------------------------------------------------------------------------
__global__ void softmax_kernel(const unsigned char* __restrict__ pad,
                               float* __restrict__ attn) {
    __shared__ float red[1024];
    const int b = blockIdx.x;
    const int tid = threadIdx.x;

    float mx = -INFINITY;
    for (int s = tid; s < SS; s += 1024) {
        float sc = pad[b * SS + s] ? -INFINITY : g_scores[b * SS + s];
        mx = fmaxf(mx, sc);
    }
    red[tid] = mx;
    __syncthreads();
    for (int off = 512; off > 0; off >>= 1) {
        if (tid < off) red[tid] = fmaxf(red[tid], red[tid + off]);
        __syncthreads();
    }
    mx = red[0];
    __syncthreads();

    float sum = 0.0f;
    for (int s = tid; s < SS; s += 1024) {
        float sc = pad[b * SS + s] ? -INFINITY : g_scores[b * SS + s];
        float e = expf(sc - mx);
        attn[b * SS + s] = e;
        sum += e;
    }
    red[tid] = sum;
    __syncthreads();
    for (int off = 512; off > 0; off >>= 1) {
        if (tid < off) red[tid] += red[tid + off];
        __syncthreads();
    }
    float inv = 1.0f / red[0];
    for (int s = tid; s < SS; s += 1024) attn[b * SS + s] *= inv;
}

// ---------------------------------------------------------------------------
// context[b][d] = sum_s attn[b][s] * memory[b][s][d]. grid=(B,32), block=512.
// ---------------------------------------------------------------------------
__global__ void context_kernel(const float* __restrict__ memory,
                               const float* __restrict__ attn,
                               float* __restrict__ ctx) {
    __shared__ float w[128];
    const int b = blockIdx.x;
    const int s0 = blockIdx.y * 128;
    const int d = threadIdx.x;

    if (d < 128) w[d] = attn[b * SS + s0 + d];
    __syncthreads();

    float acc = 0.0f;
    const float* mbase = memory + ((long)b * SS + s0) * MEMD + d;
#pragma unroll 4
    for (int s = 0; s < 128; s++) acc += w[s] * mbase[(long)s * MEMD];
    atomicAdd(&ctx[b * MEMD + d], acc);
}

// ---------------------------------------------------------------------------
// Launch.  Inputs (metadata order):
//   0 hidden | 1 memory | 2 mem_pad | 3 coverage | 4 W_h | 5 W_m | 6 W_c | 7 v
// Output: [context (B*MEM) | attn (B*S)] f32
// ---------------------------------------------------------------------------
extern "C" void kernel_launch(void* const* d_in, const int* in_sizes, int n_in,
                              void* d_out, int out_size) {
    const float* hidden   = (const float*)d_in[0];
    const float* memory   = (const float*)d_in[1];
    const unsigned char* mem_pad = (const unsigned char*)d_in[2];
    const float* coverage = (const float*)d_in[3];
    const float* W_h      = (const float*)d_in[4];
    const float* W_m      = (const float*)d_in[5];
    const float* W_c      = (const float*)d_in[6];
    const float* v        = (const float*)d_in[7];

    float* out = (float*)d_out;
    float* out_ctx  = out;
    float* out_attn = out + BB * MEMD;

    cudaFuncSetAttribute(score_mma, cudaFuncAttributeMaxDynamicSharedMemorySize,
                         SMEM_DYN);

    zero_kernel<<<(BB * SS + 255) / 256, 256>>>(out_ctx);
    permute_wm16<<<(2 * 16 * 8 * 128 * 4 + 255) / 256, 256>>>(W_m);
    h_kernel<<<BB, 512>>>(hidden, W_h);
    {
        dim3 grid(ATT / BN, BB * SS / BM);
        score_mma<<<grid, 512, SMEM_DYN>>>(memory, coverage, W_c, v);
    }
    softmax_kernel<<<BB, 1024>>>(mem_pad, out_attn);
    {
        dim3 grid(BB, SS / 128);
        context_kernel<<<grid, 512>>>(memory, out_attn, out_ctx);
    }
}

// round 8
// speedup vs baseline: 4.7118x; 1.1743x over previous
#include <cuda_runtime.h>
#include <cuda_fp16.h>
#include <math.h>
#include <stdint.h>

#define BB   32
#define SS   4096
#define HID  512
#define MEMD 512
#define ATT  512

// ------------------------------- scratch -----------------------------------
__device__ float g_scores[BB * SS];
__device__ float g_h[BB * ATT];
// W_m permuted into per-thread fp16 fragment order for m16n8k16, BN=128 tiles.
// uint (half2) layout: [n0t(4)][stage(16)][i8(8)][chunk(64)][e(4)]
//   i8 = kk*4 + kb*2 + jq ; j = jq*4 + e ; chunk = warpN*32 + lane
//   half2 = { W[k][n], W[k+1][n] },  k = s*32 + kk*16 + kb*8 + 2*tg
//   n = n0t*128 + warpN*64 + j*8 + g
__device__ unsigned int g_Wp16[4 * 16 * 8 * 64 * 4];

// ------------------------------- helpers -----------------------------------
__device__ __forceinline__ uint32_t smem_u32(const void* p) {
    return (uint32_t)__cvta_generic_to_shared(p);
}
__device__ __forceinline__ void cp16(uint32_t dst, const void* src) {
    asm volatile("cp.async.cg.shared.global [%0], [%1], 16;\n" :: "r"(dst), "l"(src));
}
__device__ __forceinline__ void cp_commit() { asm volatile("cp.async.commit_group;\n" ::: "memory"); }
template <int N>
__device__ __forceinline__ void cp_wait() {
    asm volatile("cp.async.wait_group %0;\n" :: "n"(N) : "memory");
}
// pack float2 {x=k_even, y=k_odd} -> f16x2 reg (lo = x)
__device__ __forceinline__ uint32_t pack_f16x2(float2 p) {
    uint32_t d;
    asm("cvt.rn.f16x2.f32 %0, %1, %2;" : "=r"(d) : "f"(p.y), "f"(p.x));
    return d;
}
__device__ __forceinline__ void mma_f16(float* d, uint32_t a0, uint32_t a1,
                                        uint32_t a2, uint32_t a3,
                                        uint32_t b0, uint32_t b1) {
    asm volatile(
        "mma.sync.aligned.m16n8k16.row.col.f32.f16.f16.f32 "
        "{%0,%1,%2,%3}, {%4,%5,%6,%7}, {%8,%9}, {%0,%1,%2,%3};"
        : "+f"(d[0]), "+f"(d[1]), "+f"(d[2]), "+f"(d[3])
        : "r"(a0), "r"(a1), "r"(a2), "r"(a3), "r"(b0), "r"(b1));
}
__device__ __forceinline__ float tanh_fast(float x) {
    float y; asm("tanh.approx.f32 %0, %1;" : "=f"(y) : "f"(x)); return y;
}

// ---------------------------------------------------------------------------
// zero: scores scratch + context output region
// ---------------------------------------------------------------------------
__global__ void zero_kernel(float* __restrict__ out_ctx) {
    int i = blockIdx.x * blockDim.x + threadIdx.x;
    if (i < BB * SS) g_scores[i] = 0.0f;
    if (i < BB * MEMD) out_ctx[i] = 0.0f;
}

// ---------------------------------------------------------------------------
// Build g_Wp16 (fp16 permuted fragment layout, BN=128). One thread per half2.
// ---------------------------------------------------------------------------
__global__ void permute_wm16(const float* __restrict__ Wm) {
    int o = blockIdx.x * blockDim.x + threadIdx.x;
    if (o >= 4 * 16 * 8 * 64 * 4) return;
    int e     = o & 3;
    int chunk = (o >> 2) & 63;
    int i8    = (o >> 8) & 7;
    int s     = (o >> 11) & 15;
    int n0t   = o >> 15;
    int kk = i8 >> 2, kb = (i8 >> 1) & 1, jq = i8 & 1;
    int j = jq * 4 + e;
    int lane = chunk & 31, warpN = chunk >> 5;
    int g = lane >> 2, tg = lane & 3;
    int k = s * 32 + kk * 16 + kb * 8 + 2 * tg;
    int n = n0t * 128 + warpN * 64 + j * 8 + g;
    __half2 h = __floats2half2_rn(Wm[k * ATT + n], Wm[(k + 1) * ATT + n]);
    g_Wp16[o] = *reinterpret_cast<unsigned int*>(&h);
}

// ---------------------------------------------------------------------------
// h[b][a] = hidden[b] . W_h[:,a]   grid=B, block=512
// ---------------------------------------------------------------------------
__global__ void h_kernel(const float* __restrict__ hidden,
                         const float* __restrict__ W_h) {
    __shared__ float sh[HID];
    int b = blockIdx.x;
    int a = threadIdx.x;
    sh[a] = hidden[b * HID + a];
    __syncthreads();
    float acc = 0.0f;
#pragma unroll 8
    for (int d = 0; d < HID; d++) acc += sh[d] * W_h[d * ATT + a];
    g_h[b * ATT + a] = acc;
}

// ---------------------------------------------------------------------------
// Score GEMM (fp16 m16n8k16, fp32 accumulate) + tanh/v epilogue.
// CTA tile 128(M) x 128(N), 16 warps (8M x 2N), warp tile 16x64, 512 threads.
// A fp32 in smem (AST=40: conflict-free LDS.64); B pre-permuted fp16 LDS.128.
// 3-stage cp.async pipeline. grid = (4 n-tiles, 1024 m-tiles).
// ---------------------------------------------------------------------------
#define BM 128
#define BN 128
#define BK 32
#define AST 40                        // conflict-free for fragment LDS.64
#define A_TILE (BM * AST)             // 5120 floats / stage (20KB)
#define B_TILE_U (8 * 64 * 4)         // 2048 uints / stage (8KB)
#define NSTAGE (MEMD / BK)            // 16
#define AUX_OFF (3 * A_TILE + 3 * B_TILE_U)
#define SMEM_DYN ((AUX_OFF + 3 * 512) * 4)

__global__ void __launch_bounds__(512, 1) score_mma(
    const float* __restrict__ Amem,
    const float* __restrict__ coverage,
    const float* __restrict__ Wc,
    const float* __restrict__ vvec) {

    extern __shared__ float dsm[];
    float* As_all = dsm;                                      // 3 * A_TILE fp32
    unsigned int* Bs_all = (unsigned int*)(dsm + 3 * A_TILE); // 3 * B_TILE_U
    float* sh_h   = dsm + AUX_OFF;                            // 512 (absolute)
    float* sh_wc  = sh_h + 512;
    float* sh_v   = sh_wc + 512;

    const int tid   = threadIdx.x;
    const int lane  = tid & 31;
    const int wid   = tid >> 5;     // 0..15
    const int warpN = wid & 1;      // 0..1
    const int warpM = wid >> 1;     // 0..7
    const int g     = lane >> 2;    // 0..7
    const int tg    = lane & 3;     // 0..3
    const int chunkB = warpN * 32 + lane;

    const int  n0t  = blockIdx.x;
    const int  n0   = n0t * BN;
    const long row0 = (long)blockIdx.y * BM;
    const int  b    = (int)(row0 >> 12);

    if (tid < 512) {
        sh_h[tid]  = g_h[b * 512 + tid];
        sh_wc[tid] = Wc[tid];
        sh_v[tid]  = vvec[tid];
    }

    float acc[8][4];
#pragma unroll
    for (int j = 0; j < 8; j++)
#pragma unroll
        for (int c = 0; c < 4; c++) acc[j][c] = 0.0f;

    const unsigned int* BsrcBase = g_Wp16 + (long)n0t * 16 * B_TILE_U;

    auto load_stage = [&](int s) {
        const int buf = s % 3;
        uint32_t Abu = smem_u32(As_all + buf * A_TILE);
        uint32_t Bbu = smem_u32(Bs_all + buf * B_TILE_U);
        const int k0 = s * BK;
        // A: 128 rows x 8 float4 = 1024 cp16 over 512 threads -> 2 each
#pragma unroll
        for (int j = 0; j < 2; j++) {
            int c = tid + 512 * j;
            int r = c >> 3, c4 = c & 7;
            cp16(Abu + (r * AST + c4 * 4) * 4, Amem + (row0 + r) * 512 + k0 + c4 * 4);
        }
        // B: 512 uint4 -> 1 each (coalesced)
        const unsigned int* Bsrc = BsrcBase + (long)s * B_TILE_U;
        cp16(Bbu + tid * 16, Bsrc + tid * 4);
        cp_commit();
    };

    load_stage(0);
    load_stage(1);

    for (int s = 0; s < NSTAGE; s++) {
        if (s < NSTAGE - 1) cp_wait<1>(); else cp_wait<0>();
        __syncthreads();
        if (s + 2 < NSTAGE) load_stage(s + 2);

        const int buf = s % 3;
        const float* Ab = As_all + buf * A_TILE;
        const uint4* B4 = (const uint4*)(Bs_all + buf * B_TILE_U);

#pragma unroll
        for (int kk = 0; kk < 2; kk++) {
            // B fragments: 4x LDS.128 (sequential, conflict-free)
            uint4 q0 = B4[(kk * 4 + 0) * 64 + chunkB];  // b0, j0-3
            uint4 q1 = B4[(kk * 4 + 1) * 64 + chunkB];  // b0, j4-7
            uint4 q2 = B4[(kk * 4 + 2) * 64 + chunkB];  // b1, j0-3
            uint4 q3 = B4[(kk * 4 + 3) * 64 + chunkB];  // b1, j4-7
            uint32_t b0[8] = {q0.x, q0.y, q0.z, q0.w, q1.x, q1.y, q1.z, q1.w};
            uint32_t b1[8] = {q2.x, q2.y, q2.z, q2.w, q3.x, q3.y, q3.z, q3.w};

            // A fragments: 4x LDS.64, conflict-free with AST=40
            const int r = warpM * 16 + g;
            const int kbase = kk * 16 + 2 * tg;
            float2 p0 = *(const float2*)(Ab + r * AST + kbase);
            float2 p1 = *(const float2*)(Ab + (r + 8) * AST + kbase);
            float2 p2 = *(const float2*)(Ab + r * AST + kbase + 8);
            float2 p3 = *(const float2*)(Ab + (r + 8) * AST + kbase + 8);
            uint32_t a0 = pack_f16x2(p0);
            uint32_t a1 = pack_f16x2(p1);
            uint32_t a2 = pack_f16x2(p2);
            uint32_t a3 = pack_f16x2(p3);
#pragma unroll
            for (int j = 0; j < 8; j++)
                mma_f16(acc[j], a0, a1, a2, a3, b0[j], b1[j]);
        }
    }

    // ---- epilogue: tanh + v-dot partial over this CTA's 128 n-cols ----
    {
        const int r_lo = warpM * 16 + g;
        const int r_hi = r_lo + 8;
        const float cov_lo = coverage[row0 + r_lo];
        const float cov_hi = coverage[row0 + r_hi];
        float p_lo = 0.0f, p_hi = 0.0f;
#pragma unroll
        for (int j = 0; j < 8; j++) {
            const int nb = n0 + warpN * 64 + j * 8 + tg * 2;  // absolute col
            const float h0 = sh_h[nb + 0], h1 = sh_h[nb + 1];
            const float w0 = sh_wc[nb + 0], w1 = sh_wc[nb + 1];
            const float v0 = sh_v[nb + 0], v1 = sh_v[nb + 1];
            p_lo += tanh_fast(acc[j][0] + h0 + cov_lo * w0) * v0;
            p_lo += tanh_fast(acc[j][1] + h1 + cov_lo * w1) * v1;
            p_hi += tanh_fast(acc[j][2] + h0 + cov_hi * w0) * v0;
            p_hi += tanh_fast(acc[j][3] + h1 + cov_hi * w1) * v1;
        }
        p_lo += __shfl_xor_sync(0xffffffffu, p_lo, 1);
        p_lo += __shfl_xor_sync(0xffffffffu, p_lo, 2);
        p_hi += __shfl_xor_sync(0xffffffffu, p_hi, 1);
        p_hi += __shfl_xor_sync(0xffffffffu, p_hi, 2);
        if (tg == 0) {
            atomicAdd(&g_scores[row0 + r_lo], p_lo);
            atomicAdd(&g_scores[row0 + r_hi], p_hi);
        }
    }
}

// ---------------------------------------------------------------------------
// Softmax over S per batch (with pad mask). grid=B, block=1024.
// ---------------------------------------------------------------------------
__global__ void softmax_kernel(const unsigned char* __restrict__ pad,
                               float* __restrict__ attn) {
    __shared__ float red[1024];
    const int b = blockIdx.x;
    const int tid = threadIdx.x;

    float mx = -INFINITY;
    for (int s = tid; s < SS; s += 1024) {
        float sc = pad[b * SS + s] ? -INFINITY : g_scores[b * SS + s];
        mx = fmaxf(mx, sc);
    }
    red[tid] = mx;
    __syncthreads();
    for (int off = 512; off > 0; off >>= 1) {
        if (tid < off) red[tid] = fmaxf(red[tid], red[tid + off]);
        __syncthreads();
    }
    mx = red[0];
    __syncthreads();

    float sum = 0.0f;
    for (int s = tid; s < SS; s += 1024) {
        float sc = pad[b * SS + s] ? -INFINITY : g_scores[b * SS + s];
        float e = expf(sc - mx);
        attn[b * SS + s] = e;
        sum += e;
    }
    red[tid] = sum;
    __syncthreads();
    for (int off = 512; off > 0; off >>= 1) {
        if (tid < off) red[tid] += red[tid + off];
        __syncthreads();
    }
    float inv = 1.0f / red[0];
    for (int s = tid; s < SS; s += 1024) attn[b * SS + s] *= inv;
}

// ---------------------------------------------------------------------------
// context[b][d] = sum_s attn[b][s] * memory[b][s][d]. grid=(B,32), block=512.
// ---------------------------------------------------------------------------
__global__ void context_kernel(const float* __restrict__ memory,
                               const float* __restrict__ attn,
                               float* __restrict__ ctx) {
    __shared__ float w[128];
    const int b = blockIdx.x;
    const int s0 = blockIdx.y * 128;
    const int d = threadIdx.x;

    if (d < 128) w[d] = attn[b * SS + s0 + d];
    __syncthreads();

    float acc = 0.0f;
    const float* mbase = memory + ((long)b * SS + s0) * MEMD + d;
#pragma unroll 4
    for (int s = 0; s < 128; s++) acc += w[s] * mbase[(long)s * MEMD];
    atomicAdd(&ctx[b * MEMD + d], acc);
}

// ---------------------------------------------------------------------------
// Launch.  Inputs (metadata order):
//   0 hidden | 1 memory | 2 mem_pad | 3 coverage | 4 W_h | 5 W_m | 6 W_c | 7 v
// Output: [context (B*MEM) | attn (B*S)] f32
// ---------------------------------------------------------------------------
extern "C" void kernel_launch(void* const* d_in, const int* in_sizes, int n_in,
                              void* d_out, int out_size) {
    const float* hidden   = (const float*)d_in[0];
    const float* memory   = (const float*)d_in[1];
    const unsigned char* mem_pad = (const unsigned char*)d_in[2];
    const float* coverage = (const float*)d_in[3];
    const float* W_h      = (const float*)d_in[4];
    const float* W_m      = (const float*)d_in[5];
    const float* W_c      = (const float*)d_in[6];
    const float* v        = (const float*)d_in[7];

    float* out = (float*)d_out;
    float* out_ctx  = out;
    float* out_attn = out + BB * MEMD;

    cudaFuncSetAttribute(score_mma, cudaFuncAttributeMaxDynamicSharedMemorySize,
                         SMEM_DYN);

    zero_kernel<<<(BB * SS + 255) / 256, 256>>>(out_ctx);
    permute_wm16<<<(4 * 16 * 8 * 64 * 4 + 255) / 256, 256>>>(W_m);
    h_kernel<<<BB, 512>>>(hidden, W_h);
    {
        dim3 grid(ATT / BN, BB * SS / BM);
        score_mma<<<grid, 512, SMEM_DYN>>>(memory, coverage, W_c, v);
    }
    softmax_kernel<<<BB, 1024>>>(mem_pad, out_attn);
    {
        dim3 grid(BB, SS / 128);
        context_kernel<<<grid, 512>>>(memory, out_attn, out_ctx);
    }
}

// round 9
// speedup vs baseline: 5.1090x; 1.0843x over previous
#include <cuda_runtime.h>
#include <cuda_fp16.h>
#include <math.h>
#include <stdint.h>

#define BB   32
#define SS   4096
#define HID  512
#define MEMD 512
#define ATT  512

// ------------------------------- scratch -----------------------------------
__device__ float g_scores[BB * SS];
__device__ float g_h[BB * ATT];
// W_m permuted into per-thread fp16 fragment order for m16n8k16, BN=128 tiles.
// uint (half2) layout: [n0t(4)][stage(16)][i8(8)][chunk(64)][e(4)]
//   i8 = kk*4 + kb*2 + jq ; j = jq*4 + e ; chunk = warpN*32 + lane
//   half2 = { W[k][n], W[k+1][n] },  k = s*32 + kk*16 + kb*8 + 2*tg
//   n = n0t*128 + warpN*64 + j*8 + g
__device__ unsigned int g_Wp16[4 * 16 * 8 * 64 * 4];

// ------------------------------- helpers -----------------------------------
__device__ __forceinline__ uint32_t smem_u32(const void* p) {
    return (uint32_t)__cvta_generic_to_shared(p);
}
__device__ __forceinline__ void cp16(uint32_t dst, const void* src) {
    asm volatile("cp.async.cg.shared.global [%0], [%1], 16;\n" :: "r"(dst), "l"(src));
}
__device__ __forceinline__ void cp_commit() { asm volatile("cp.async.commit_group;\n" ::: "memory"); }
template <int N>
__device__ __forceinline__ void cp_wait() {
    asm volatile("cp.async.wait_group %0;\n" :: "n"(N) : "memory");
}
// pack float2 {x=k_even, y=k_odd} -> f16x2 reg (lo = x)
__device__ __forceinline__ uint32_t pack_f16x2(float2 p) {
    uint32_t d;
    asm("cvt.rn.f16x2.f32 %0, %1, %2;" : "=r"(d) : "f"(p.y), "f"(p.x));
    return d;
}
__device__ __forceinline__ void mma_f16(float* d, uint32_t a0, uint32_t a1,
                                        uint32_t a2, uint32_t a3,
                                        uint32_t b0, uint32_t b1) {
    asm volatile(
        "mma.sync.aligned.m16n8k16.row.col.f32.f16.f16.f32 "
        "{%0,%1,%2,%3}, {%4,%5,%6,%7}, {%8,%9}, {%0,%1,%2,%3};"
        : "+f"(d[0]), "+f"(d[1]), "+f"(d[2]), "+f"(d[3])
        : "r"(a0), "r"(a1), "r"(a2), "r"(a3), "r"(b0), "r"(b1));
}
__device__ __forceinline__ float tanh_fast(float x) {
    float y; asm("tanh.approx.f32 %0, %1;" : "=f"(y) : "f"(x)); return y;
}

// ---------------------------------------------------------------------------
// zero: scores scratch + context output region
// ---------------------------------------------------------------------------
__global__ void zero_kernel(float* __restrict__ out_ctx) {
    int i = blockIdx.x * blockDim.x + threadIdx.x;
    if (i < BB * SS) g_scores[i] = 0.0f;
    if (i < BB * MEMD) out_ctx[i] = 0.0f;
}

// ---------------------------------------------------------------------------
// Build g_Wp16 (fp16 permuted fragment layout, BN=128). One thread per half2.
// ---------------------------------------------------------------------------
__global__ void permute_wm16(const float* __restrict__ Wm) {
    int o = blockIdx.x * blockDim.x + threadIdx.x;
    if (o >= 4 * 16 * 8 * 64 * 4) return;
    int e     = o & 3;
    int chunk = (o >> 2) & 63;
    int i8    = (o >> 8) & 7;
    int s     = (o >> 11) & 15;
    int n0t   = o >> 15;
    int kk = i8 >> 2, kb = (i8 >> 1) & 1, jq = i8 & 1;
    int j = jq * 4 + e;
    int lane = chunk & 31, warpN = chunk >> 5;
    int g = lane >> 2, tg = lane & 3;
    int k = s * 32 + kk * 16 + kb * 8 + 2 * tg;
    int n = n0t * 128 + warpN * 64 + j * 8 + g;
    __half2 h = __floats2half2_rn(Wm[k * ATT + n], Wm[(k + 1) * ATT + n]);
    g_Wp16[o] = *reinterpret_cast<unsigned int*>(&h);
}

// ---------------------------------------------------------------------------
// h[b][a] = hidden[b] . W_h[:,a]   grid=B, block=512
// ---------------------------------------------------------------------------
__global__ void h_kernel(const float* __restrict__ hidden,
                         const float* __restrict__ W_h) {
    __shared__ float sh[HID];
    int b = blockIdx.x;
    int a = threadIdx.x;
    sh[a] = hidden[b * HID + a];
    __syncthreads();
    float acc = 0.0f;
#pragma unroll 8
    for (int d = 0; d < HID; d++) acc += sh[d] * W_h[d * ATT + a];
    g_h[b * ATT + a] = acc;
}

// ---------------------------------------------------------------------------
// Score GEMM (fp16 m16n8k16, fp32 accumulate) + tanh/v epilogue.
// CTA tile 128(M) x 128(N), 8 warps (4M x 2N), warp tile 32x64, 256 threads.
// 2 CTAs/SM. A fp32 in smem (AST=40, conflict-free); B pre-permuted fp16.
// 3-stage cp.async pipeline. grid = (4 n-tiles, 1024 m-tiles).
// ---------------------------------------------------------------------------
#define BM 128
#define BN 128
#define BK 32
#define AST 40                        // conflict-free for fragment LDS.64
#define A_TILE (BM * AST)             // 5120 floats / stage (20KB)
#define B_TILE_U (8 * 64 * 4)         // 2048 uints / stage (8KB)
#define NSTAGE (MEMD / BK)            // 16
#define AUX_OFF (3 * A_TILE + 3 * B_TILE_U)
#define SMEM_DYN ((AUX_OFF + 3 * 512) * 4)

__global__ void __launch_bounds__(256, 2) score_mma(
    const float* __restrict__ Amem,
    const float* __restrict__ coverage,
    const float* __restrict__ Wc,
    const float* __restrict__ vvec) {

    extern __shared__ float dsm[];
    float* As_all = dsm;                                      // 3 * A_TILE fp32
    unsigned int* Bs_all = (unsigned int*)(dsm + 3 * A_TILE); // 3 * B_TILE_U
    float* sh_h   = dsm + AUX_OFF;                            // 512 (absolute)
    float* sh_wc  = sh_h + 512;
    float* sh_v   = sh_wc + 512;

    const int tid   = threadIdx.x;
    const int lane  = tid & 31;
    const int wid   = tid >> 5;     // 0..7
    const int warpN = wid & 1;      // 0..1
    const int warpM = wid >> 1;     // 0..3
    const int g     = lane >> 2;    // 0..7
    const int tg    = lane & 3;     // 0..3
    const int chunkB = warpN * 32 + lane;

    const int  n0t  = blockIdx.x;
    const int  n0   = n0t * BN;
    const long row0 = (long)blockIdx.y * BM;
    const int  b    = (int)(row0 >> 12);

    for (int i = tid; i < 512; i += 256) {
        sh_h[i]  = g_h[b * 512 + i];
        sh_wc[i] = Wc[i];
        sh_v[i]  = vvec[i];
    }

    float acc[2][8][4];
#pragma unroll
    for (int i = 0; i < 2; i++)
#pragma unroll
        for (int j = 0; j < 8; j++)
#pragma unroll
            for (int c = 0; c < 4; c++) acc[i][j][c] = 0.0f;

    const unsigned int* BsrcBase = g_Wp16 + (long)n0t * 16 * B_TILE_U;

    auto load_stage = [&](int s) {
        const int buf = s % 3;
        uint32_t Abu = smem_u32(As_all + buf * A_TILE);
        uint32_t Bbu = smem_u32(Bs_all + buf * B_TILE_U);
        const int k0 = s * BK;
        // A: 128 rows x 8 float4 = 1024 cp16 over 256 threads -> 4 each
#pragma unroll
        for (int j = 0; j < 4; j++) {
            int c = tid + 256 * j;
            int r = c >> 3, c4 = c & 7;
            cp16(Abu + (r * AST + c4 * 4) * 4, Amem + (row0 + r) * 512 + k0 + c4 * 4);
        }
        // B: 512 uint4 -> 2 each (coalesced)
        const unsigned int* Bsrc = BsrcBase + (long)s * B_TILE_U;
#pragma unroll
        for (int j = 0; j < 2; j++) {
            int u4 = tid + 256 * j;
            cp16(Bbu + u4 * 16, Bsrc + u4 * 4);
        }
        cp_commit();
    };

    load_stage(0);
    load_stage(1);

    for (int s = 0; s < NSTAGE; s++) {
        if (s < NSTAGE - 1) cp_wait<1>(); else cp_wait<0>();
        __syncthreads();
        if (s + 2 < NSTAGE) load_stage(s + 2);

        const int buf = s % 3;
        const float* Ab = As_all + buf * A_TILE;
        const uint4* B4 = (const uint4*)(Bs_all + buf * B_TILE_U);

#pragma unroll
        for (int kk = 0; kk < 2; kk++) {
            // B fragments: 4x LDS.128 (conflict-free)
            uint4 q0 = B4[(kk * 4 + 0) * 64 + chunkB];  // b0, j0-3
            uint4 q1 = B4[(kk * 4 + 1) * 64 + chunkB];  // b0, j4-7
            uint4 q2 = B4[(kk * 4 + 2) * 64 + chunkB];  // b1, j0-3
            uint4 q3 = B4[(kk * 4 + 3) * 64 + chunkB];  // b1, j4-7
            uint32_t b0[8] = {q0.x, q0.y, q0.z, q0.w, q1.x, q1.y, q1.z, q1.w};
            uint32_t b1[8] = {q2.x, q2.y, q2.z, q2.w, q3.x, q3.y, q3.z, q3.w};

#pragma unroll
            for (int i = 0; i < 2; i++) {
                // A fragments: 4x LDS.64, conflict-free with AST=40
                const int r = warpM * 32 + i * 16 + g;
                const int kbase = kk * 16 + 2 * tg;
                float2 p0 = *(const float2*)(Ab + r * AST + kbase);
                float2 p1 = *(const float2*)(Ab + (r + 8) * AST + kbase);
                float2 p2 = *(const float2*)(Ab + r * AST + kbase + 8);
                float2 p3 = *(const float2*)(Ab + (r + 8) * AST + kbase + 8);
                uint32_t a0 = pack_f16x2(p0);
                uint32_t a1 = pack_f16x2(p1);
                uint32_t a2 = pack_f16x2(p2);
                uint32_t a3 = pack_f16x2(p3);
#pragma unroll
                for (int j = 0; j < 8; j++)
                    mma_f16(acc[i][j], a0, a1, a2, a3, b0[j], b1[j]);
            }
        }
    }

    // ---- epilogue: tanh + v-dot partial over this CTA's 128 n-cols ----
#pragma unroll
    for (int i = 0; i < 2; i++) {
        const int r_lo = warpM * 32 + i * 16 + g;
        const int r_hi = r_lo + 8;
        const float cov_lo = coverage[row0 + r_lo];
        const float cov_hi = coverage[row0 + r_hi];
        float p_lo = 0.0f, p_hi = 0.0f;
#pragma unroll
        for (int j = 0; j < 8; j++) {
            const int nb = n0 + warpN * 64 + j * 8 + tg * 2;  // absolute col
            const float h0 = sh_h[nb + 0], h1 = sh_h[nb + 1];
            const float w0 = sh_wc[nb + 0], w1 = sh_wc[nb + 1];
            const float v0 = sh_v[nb + 0], v1 = sh_v[nb + 1];
            p_lo += tanh_fast(acc[i][j][0] + h0 + cov_lo * w0) * v0;
            p_lo += tanh_fast(acc[i][j][1] + h1 + cov_lo * w1) * v1;
            p_hi += tanh_fast(acc[i][j][2] + h0 + cov_hi * w0) * v0;
            p_hi += tanh_fast(acc[i][j][3] + h1 + cov_hi * w1) * v1;
        }
        p_lo += __shfl_xor_sync(0xffffffffu, p_lo, 1);
        p_lo += __shfl_xor_sync(0xffffffffu, p_lo, 2);
        p_hi += __shfl_xor_sync(0xffffffffu, p_hi, 1);
        p_hi += __shfl_xor_sync(0xffffffffu, p_hi, 2);
        if (tg == 0) {
            atomicAdd(&g_scores[row0 + r_lo], p_lo);
            atomicAdd(&g_scores[row0 + r_hi], p_hi);
        }
    }
}

// ---------------------------------------------------------------------------
// Softmax over S per batch (with pad mask). grid=B, block=1024.
// ---------------------------------------------------------------------------
__global__ void softmax_kernel(const unsigned char* __restrict__ pad,
                               float* __restrict__ attn) {
    __shared__ float red[1024];
    const int b = blockIdx.x;
    const int tid = threadIdx.x;

    float mx = -INFINITY;
    for (int s = tid; s < SS; s += 1024) {
        float sc = pad[b * SS + s] ? -INFINITY : g_scores[b * SS + s];
        mx = fmaxf(mx, sc);
    }
    red[tid] = mx;
    __syncthreads();
    for (int off = 512; off > 0; off >>= 1) {
        if (tid < off) red[tid] = fmaxf(red[tid], red[tid + off]);
        __syncthreads();
    }
    mx = red[0];
    __syncthreads();

    float sum = 0.0f;
    for (int s = tid; s < SS; s += 1024) {
        float sc = pad[b * SS + s] ? -INFINITY : g_scores[b * SS + s];
        float e = expf(sc - mx);
        attn[b * SS + s] = e;
        sum += e;
    }
    red[tid] = sum;
    __syncthreads();
    for (int off = 512; off > 0; off >>= 1) {
        if (tid < off) red[tid] += red[tid + off];
        __syncthreads();
    }
    float inv = 1.0f / red[0];
    for (int s = tid; s < SS; s += 1024) attn[b * SS + s] *= inv;
}

// ---------------------------------------------------------------------------
// context[b][d] = sum_s attn[b][s] * memory[b][s][d]. grid=(B,32), block=512.
// ---------------------------------------------------------------------------
__global__ void context_kernel(const float* __restrict__ memory,
                               const float* __restrict__ attn,
                               float* __restrict__ ctx) {
    __shared__ float w[128];
    const int b = blockIdx.x;
    const int s0 = blockIdx.y * 128;
    const int d = threadIdx.x;

    if (d < 128) w[d] = attn[b * SS + s0 + d];
    __syncthreads();

    float acc = 0.0f;
    const float* mbase = memory + ((long)b * SS + s0) * MEMD + d;
#pragma unroll 4
    for (int s = 0; s < 128; s++) acc += w[s] * mbase[(long)s * MEMD];
    atomicAdd(&ctx[b * MEMD + d], acc);
}

// ---------------------------------------------------------------------------
// Launch.  Inputs (metadata order):
//   0 hidden | 1 memory | 2 mem_pad | 3 coverage | 4 W_h | 5 W_m | 6 W_c | 7 v
// Output: [context (B*MEM) | attn (B*S)] f32
// ---------------------------------------------------------------------------
extern "C" void kernel_launch(void* const* d_in, const int* in_sizes, int n_in,
                              void* d_out, int out_size) {
    const float* hidden   = (const float*)d_in[0];
    const float* memory   = (const float*)d_in[1];
    const unsigned char* mem_pad = (const unsigned char*)d_in[2];
    const float* coverage = (const float*)d_in[3];
    const float* W_h      = (const float*)d_in[4];
    const float* W_m      = (const float*)d_in[5];
    const float* W_c      = (const float*)d_in[6];
    const float* v        = (const float*)d_in[7];

    float* out = (float*)d_out;
    float* out_ctx  = out;
    float* out_attn = out + BB * MEMD;

    cudaFuncSetAttribute(score_mma, cudaFuncAttributeMaxDynamicSharedMemorySize,
                         SMEM_DYN);

    zero_kernel<<<(BB * SS + 255) / 256, 256>>>(out_ctx);
    permute_wm16<<<(4 * 16 * 8 * 64 * 4 + 255) / 256, 256>>>(W_m);
    h_kernel<<<BB, 512>>>(hidden, W_h);
    {
        dim3 grid(ATT / BN, BB * SS / BM);
        score_mma<<<grid, 256, SMEM_DYN>>>(memory, coverage, W_c, v);
    }
    softmax_kernel<<<BB, 1024>>>(mem_pad, out_attn);
    {
        dim3 grid(BB, SS / 128);
        context_kernel<<<grid, 512>>>(memory, out_attn, out_ctx);
    }
}